// round 2
// baseline (speedup 1.0000x reference)
#include <cuda_runtime.h>
#include <cuda_bf16.h>
#include <stdint.h>

// Problem constants (fixed shapes for this problem instance)
#define NN 50000       // nodes
#define EE 800000      // edges
#define MM 8           // B*T
#define CC 32          // in channels
#define OO 32          // out channels
#define FF 256         // MM*CC features per node
#define BN_EPS 1e-5f

// ---------------- scratch (device globals; no allocation allowed) -------------
__device__ float g_deg[NN];
__device__ float g_dinv[NN];
__device__ int   g_cnt[NN];          // histogram by dst, reused as fill cursor
__device__ int   g_rowptr[NN + 1];
__device__ int   g_csrc[EE];
__device__ float g_cw[EE];
__device__ __align__(16) float g_t1[(size_t)NN * FF];     // L x
__device__ __align__(16) float g_t2[(size_t)NN * FF];     // L (L x)  (raw)
__device__ __align__(16) float g_outpre[(size_t)NN * FF]; // pre-BN [n][m][o]
__device__ float g_bnsum[MM * OO];
__device__ float g_bnsq[MM * OO];
__device__ float g_scale[MM * OO];
__device__ float g_shift[MM * OO];

// ---------------- 0: zero degree / counts / BN sums ---------------------------
__global__ void k_zero() {
    int i = blockIdx.x * blockDim.x + threadIdx.x;
    if (i < NN) { g_deg[i] = 0.f; g_cnt[i] = 0; }
    if (i < MM * OO) { g_bnsum[i] = 0.f; g_bnsq[i] = 0.f; }
}

// ---------------- 1: degree by src, edge count by dst --------------------------
// edge_index delivered as int32 by the harness (no int64 input path).
__global__ void k_degcnt(const int* __restrict__ ei,
                         const float* __restrict__ ew) {
    int e = blockIdx.x * blockDim.x + threadIdx.x;
    if (e >= EE) return;
    int s = ei[e];
    int d = ei[EE + e];
    atomicAdd(&g_deg[s], ew[e]);
    atomicAdd(&g_cnt[d], 1);
}

// ---------------- 2: dinv = deg>0 ? rsqrt(deg) : 0 -----------------------------
__global__ void k_dinv() {
    int i = blockIdx.x * blockDim.x + threadIdx.x;
    if (i >= NN) return;
    float dg = g_deg[i];
    g_dinv[i] = (dg > 0.f) ? rsqrtf(dg) : 0.f;
}

// ---------------- 3: exclusive scan of cnt -> rowptr (single block) ------------
// 1024 threads, 4 elements/thread per 4096-chunk. Also zeroes cnt so it can be
// reused as the per-row fill cursor in k_fill.
__global__ void k_scan() {
    __shared__ int warpsums[32];
    __shared__ int s_carry;
    if (threadIdx.x == 0) s_carry = 0;
    __syncthreads();
    int lane = threadIdx.x & 31, wid = threadIdx.x >> 5;
    for (int base = 0; base < NN; base += 4096) {
        int idx0 = base + threadIdx.x * 4;
        int v[4];
        #pragma unroll
        for (int j = 0; j < 4; j++) {
            int i = idx0 + j;
            if (i < NN) { v[j] = g_cnt[i]; g_cnt[i] = 0; } else v[j] = 0;
        }
        int tsum = v[0] + v[1] + v[2] + v[3];
        int sc = tsum;
        #pragma unroll
        for (int off = 1; off < 32; off <<= 1) {
            int t = __shfl_up_sync(0xffffffffu, sc, off);
            if (lane >= off) sc += t;
        }
        if (lane == 31) warpsums[wid] = sc;
        __syncthreads();
        if (wid == 0) {
            int ws = warpsums[lane];
            #pragma unroll
            for (int off = 1; off < 32; off <<= 1) {
                int t = __shfl_up_sync(0xffffffffu, ws, off);
                if (lane >= off) ws += t;
            }
            warpsums[lane] = ws;
        }
        __syncthreads();
        int carry = s_carry;
        int excl = carry + (wid > 0 ? warpsums[wid - 1] : 0) + sc - tsum;
        int run = excl;
        #pragma unroll
        for (int j = 0; j < 4; j++) {
            int i = idx0 + j;
            if (i < NN) { run += v[j]; g_rowptr[i + 1] = run; }
        }
        __syncthreads();
        if (threadIdx.x == 0) s_carry = carry + warpsums[31];
        __syncthreads();
    }
    if (threadIdx.x == 0) g_rowptr[0] = 0;
}

// ---------------- 4: CSR fill (edges grouped by dst) ---------------------------
__global__ void k_fill(const int* __restrict__ ei,
                       const float* __restrict__ ew) {
    int e = blockIdx.x * blockDim.x + threadIdx.x;
    if (e >= EE) return;
    int s = ei[e];
    int d = ei[EE + e];
    float nv = -g_dinv[s] * ew[e] * g_dinv[d];
    int pos = atomicAdd(&g_cnt[d], 1);
    int idx = g_rowptr[d] + pos;
    g_csrc[idx] = s;
    g_cw[idx] = nv;
}

// ---------------- 5: SpMM: out[dst] = sum_e w_e * in[src] ----------------------
// One warp per dst row; each lane owns 8 contiguous features (2 float4).
// MODE 0: gather from x (layout [m][n][c], i.e. [B,T,N,C] flattened) -> g_t1
// MODE 1: gather from g_t1 (node-major [n][256]) -> g_t2
template <int MODE>
__global__ void k_spmm(const float* __restrict__ x) {
    int gwarp = (blockIdx.x * blockDim.x + threadIdx.x) >> 5;
    int lane = threadIdx.x & 31;
    if (gwarp >= NN) return;
    int beg = g_rowptr[gwarp];
    int end = g_rowptr[gwarp + 1];

    float4 a0 = make_float4(0.f, 0.f, 0.f, 0.f);
    float4 a1 = make_float4(0.f, 0.f, 0.f, 0.f);

    const float4* __restrict__ xin;
    size_t laneoff;
    if (MODE == 0) {
        xin = (const float4*)x;
        int m = lane >> 2;
        laneoff = (size_t)m * NN * 8 + (size_t)(lane & 3) * 2;
    } else {
        xin = (const float4*)g_t1;
        laneoff = (size_t)lane * 2;
    }

    int e = beg;
    #pragma unroll 1
    while (e + 2 <= end) {
        int s0 = g_csrc[e], s1 = g_csrc[e + 1];
        float w0 = g_cw[e], w1 = g_cw[e + 1];
        size_t i0 = (MODE == 0) ? laneoff + (size_t)s0 * 8 : laneoff + (size_t)s0 * 64;
        size_t i1 = (MODE == 0) ? laneoff + (size_t)s1 * 8 : laneoff + (size_t)s1 * 64;
        float4 v00 = xin[i0], v01 = xin[i0 + 1];
        float4 v10 = xin[i1], v11 = xin[i1 + 1];
        a0.x += w0 * v00.x; a0.y += w0 * v00.y; a0.z += w0 * v00.z; a0.w += w0 * v00.w;
        a1.x += w0 * v01.x; a1.y += w0 * v01.y; a1.z += w0 * v01.z; a1.w += w0 * v01.w;
        a0.x += w1 * v10.x; a0.y += w1 * v10.y; a0.z += w1 * v10.z; a0.w += w1 * v10.w;
        a1.x += w1 * v11.x; a1.y += w1 * v11.y; a1.z += w1 * v11.z; a1.w += w1 * v11.w;
        e += 2;
    }
    if (e < end) {
        int s0 = g_csrc[e];
        float w0 = g_cw[e];
        size_t i0 = (MODE == 0) ? laneoff + (size_t)s0 * 8 : laneoff + (size_t)s0 * 64;
        float4 v00 = xin[i0], v01 = xin[i0 + 1];
        a0.x += w0 * v00.x; a0.y += w0 * v00.y; a0.z += w0 * v00.z; a0.w += w0 * v00.w;
        a1.x += w0 * v01.x; a1.y += w0 * v01.y; a1.z += w0 * v01.z; a1.w += w0 * v01.w;
    }

    float* outp = (MODE == 0) ? g_t1 : g_t2;
    float4* op = (float4*)&outp[(size_t)gwarp * FF + lane * 8];
    op[0] = a0;
    op[1] = a1;
}

// ---------------- 6: combine (Cheb matvecs + bias) + BN partial sums -----------
// One thread per (n, m) row. T2 = 2 * t2raw - x computed inline.
__global__ void k_combine(const float* __restrict__ x,
                          const float* __restrict__ W,
                          const float* __restrict__ bias) {
    __shared__ __align__(16) float sW[3 * CC * OO + OO];  // W0,W1,W2 + bias
    __shared__ float sSum[MM][OO];
    __shared__ float sSq[MM][OO];

    for (int i = threadIdx.x; i < 3 * CC * OO + OO; i += blockDim.x)
        sW[i] = (i < 3 * CC * OO) ? W[i] : bias[i - 3 * CC * OO];
    {
        int mi = threadIdx.x >> 5, oi = threadIdx.x & 31;
        sSum[mi][oi] = 0.f;
        sSq[mi][oi] = 0.f;
    }
    __syncthreads();

    int t = blockIdx.x * blockDim.x + threadIdx.x;
    int m = t & 7;
    bool active = (t < NN * MM);

    float4 acc[8];
    if (active) {
        int n = t >> 3;
        const float4* xp  = (const float4*)&x[((size_t)m * NN + n) * CC];
        const float4* t1p = (const float4*)&g_t1[(size_t)n * FF + m * CC];
        const float4* t2p = (const float4*)&g_t2[(size_t)n * FF + m * CC];

        #pragma unroll
        for (int o = 0; o < 8; o++)
            acc[o] = *(const float4*)&sW[3 * CC * OO + o * 4];

        #pragma unroll
        for (int q = 0; q < 8; q++) {
            float4 xv = xp[q], av = t1p[q], bv = t2p[q];
            float xs[4] = {xv.x, xv.y, xv.z, xv.w};
            float as[4] = {av.x, av.y, av.z, av.w};
            float bs[4] = {bv.x, bv.y, bv.z, bv.w};
            #pragma unroll
            for (int j = 0; j < 4; j++) {
                int cidx = q * 4 + j;
                float a = xs[j];
                float b = as[j];
                float c2 = 2.f * bs[j] - a;
                const float4* w0 = (const float4*)&sW[cidx * OO];
                const float4* w1 = (const float4*)&sW[CC * OO + cidx * OO];
                const float4* w2 = (const float4*)&sW[2 * CC * OO + cidx * OO];
                #pragma unroll
                for (int o = 0; o < 8; o++) {
                    float4 u0 = w0[o], u1 = w1[o], u2 = w2[o];
                    acc[o].x += a * u0.x + b * u1.x + c2 * u2.x;
                    acc[o].y += a * u0.y + b * u1.y + c2 * u2.y;
                    acc[o].z += a * u0.z + b * u1.z + c2 * u2.z;
                    acc[o].w += a * u0.w + b * u1.w + c2 * u2.w;
                }
            }
        }

        float4* op = (float4*)&g_outpre[(size_t)n * FF + m * CC];
        #pragma unroll
        for (int o = 0; o < 8; o++) op[o] = acc[o];

        #pragma unroll
        for (int o = 0; o < 8; o++) {
            atomicAdd(&sSum[m][o * 4 + 0], acc[o].x);
            atomicAdd(&sSum[m][o * 4 + 1], acc[o].y);
            atomicAdd(&sSum[m][o * 4 + 2], acc[o].z);
            atomicAdd(&sSum[m][o * 4 + 3], acc[o].w);
            atomicAdd(&sSq[m][o * 4 + 0], acc[o].x * acc[o].x);
            atomicAdd(&sSq[m][o * 4 + 1], acc[o].y * acc[o].y);
            atomicAdd(&sSq[m][o * 4 + 2], acc[o].z * acc[o].z);
            atomicAdd(&sSq[m][o * 4 + 3], acc[o].w * acc[o].w);
        }
    }
    __syncthreads();
    {
        int mi = threadIdx.x >> 5, oi = threadIdx.x & 31;
        atomicAdd(&g_bnsum[threadIdx.x], sSum[mi][oi]);
        atomicAdd(&g_bnsq[threadIdx.x], sSq[mi][oi]);
    }
}

// ---------------- 7: finalize BN stats -> scale/shift --------------------------
__global__ void k_finalize(const float* __restrict__ gamma,
                           const float* __restrict__ beta) {
    int i = threadIdx.x;  // 0..255 = (m, o)
    if (i >= MM * OO) return;
    int o = i & 31;
    float mean = g_bnsum[i] * (1.f / NN);
    float var = g_bnsq[i] * (1.f / NN) - mean * mean;
    float sc = gamma[o] * rsqrtf(var + BN_EPS);
    g_scale[i] = sc;
    g_shift[i] = beta[o] - mean * sc;
}

// ---------------- 8: normalize + relu + transpose to [B,T,N,O] -----------------
// One thread per output float4: t = ((m*NN + n)*8 + o4)
__global__ void k_output(float* __restrict__ out) {
    int t = blockIdx.x * blockDim.x + threadIdx.x;
    if (t >= NN * MM * 8) return;
    int o4 = t & 7;
    int nm = t >> 3;
    int n = nm % NN;
    int m = nm / NN;
    float4 v = *(const float4*)&g_outpre[((size_t)n * MM + m) * CC + o4 * 4];
    int si = m * OO + o4 * 4;
    float4 r;
    r.x = fmaxf(0.f, v.x * g_scale[si + 0] + g_shift[si + 0]);
    r.y = fmaxf(0.f, v.y * g_scale[si + 1] + g_shift[si + 1]);
    r.z = fmaxf(0.f, v.z * g_scale[si + 2] + g_shift[si + 2]);
    r.w = fmaxf(0.f, v.w * g_scale[si + 3] + g_shift[si + 3]);
    ((float4*)out)[t] = r;
}

// ------------------------------------------------------------------------------
extern "C" void kernel_launch(void* const* d_in, const int* in_sizes, int n_in,
                              void* d_out, int out_size) {
    const float* x      = (const float*)d_in[0];
    const int*   ei     = (const int*)d_in[1];     // int32 (harness dtype)
    const float* ew     = (const float*)d_in[2];
    const float* W      = (const float*)d_in[3];
    const float* bias   = (const float*)d_in[4];
    const float* gamma  = (const float*)d_in[5];
    const float* beta   = (const float*)d_in[6];
    float* out          = (float*)d_out;

    k_zero<<<(NN + 255) / 256, 256>>>();
    k_degcnt<<<(EE + 255) / 256, 256>>>(ei, ew);
    k_dinv<<<(NN + 255) / 256, 256>>>();
    k_scan<<<1, 1024>>>();
    k_fill<<<(EE + 255) / 256, 256>>>(ei, ew);
    k_spmm<0><<<(NN * 32 + 255) / 256, 256>>>(x);   // x -> t1 = Lx
    k_spmm<1><<<(NN * 32 + 255) / 256, 256>>>(x);   // t1 -> t2raw = L(Lx)
    k_combine<<<(NN * MM + 255) / 256, 256>>>(x, W, bias);
    k_finalize<<<1, 256>>>(gamma, beta);
    k_output<<<(NN * MM * 8 + 255) / 256, 256>>>(out);
}

// round 6
// speedup vs baseline: 1.1299x; 1.1299x over previous
#include <cuda_runtime.h>
#include <cuda_fp16.h>
#include <stdint.h>

// Problem constants (fixed shapes for this problem instance)
#define NN 50000       // nodes
#define EE 800000      // edges
#define MM 8           // B*T
#define CC 32          // in channels
#define OO 32          // out channels
#define FF 256         // MM*CC features per node
#define BN_EPS 1e-5f
#define SCAN_NBLK 13   // ceil(NN / 4096)

// ---------------- scratch (device globals; no allocation allowed) -------------
__device__ float g_deg[NN];
__device__ float g_dinv[NN];
__device__ int   g_cnt[NN];          // histogram by dst, reused as fill cursor
__device__ int   g_rowptr[NN + 1];
__device__ __align__(16) uint2 g_edge[EE];              // (src, bitcast weight)
__device__ __align__(16) __half g_xh[(size_t)NN * FF];  // x, node-major fp16
__device__ __align__(16) __half g_t1h[(size_t)NN * FF]; // L x (fp16)
__device__ __align__(16) __half g_t2h[(size_t)NN * FF]; // L(Lx) raw (fp16)
__device__ __align__(16) float g_outpre[(size_t)NN * FF]; // pre-BN [n][m][o]
__device__ float g_bnsum[MM * OO];
__device__ float g_bnsq[MM * OO];
__device__ float g_scale[MM * OO];
__device__ float g_shift[MM * OO];
__device__ int   g_scan_val[SCAN_NBLK];
__device__ int   g_scan_flag[SCAN_NBLK];

// ---------------- packed f32x2 helpers ----------------------------------------
__device__ __forceinline__ unsigned long long pk2(float v) {
    unsigned long long r;
    asm("mov.b64 %0, {%1, %2};" : "=l"(r) : "f"(v), "f"(v));
    return r;
}
__device__ __forceinline__ unsigned long long pk2two(float lo, float hi) {
    unsigned long long r;
    asm("mov.b64 %0, {%1, %2};" : "=l"(r) : "f"(lo), "f"(hi));
    return r;
}
__device__ __forceinline__ void unpk2(float& lo, float& hi, unsigned long long v) {
    asm("mov.b64 {%0, %1}, %2;" : "=f"(lo), "=f"(hi) : "l"(v));
}
__device__ __forceinline__ void ffma2(unsigned long long& d,
                                      unsigned long long a,
                                      unsigned long long b) {
    asm("fma.rn.f32x2 %0, %1, %2, %0;" : "+l"(d) : "l"(a), "l"(b));
}

// ---------------- 0: zero degree / counts / BN sums / scan flags ---------------
__global__ void k_zero() {
    int i = blockIdx.x * blockDim.x + threadIdx.x;
    if (i < NN) { g_deg[i] = 0.f; g_cnt[i] = 0; }
    if (i < MM * OO) { g_bnsum[i] = 0.f; g_bnsq[i] = 0.f; }
    if (i < SCAN_NBLK) g_scan_flag[i] = 0;
}

// ---------------- 1: x -> node-major fp16 [n][m*32+c] --------------------------
__global__ void k_xconv(const float* __restrict__ x) {
    int t = blockIdx.x * blockDim.x + threadIdx.x;
    if (t >= NN * MM * 16) return;
    int c2 = t & 15;
    int m = (t >> 4) & 7;
    int n = t >> 7;
    float2 v = *(const float2*)&x[((size_t)m * NN + n) * CC + c2 * 2];
    *(__half2*)&g_xh[(size_t)n * FF + m * CC + c2 * 2] = __floats2half2_rn(v.x, v.y);
}

// ---------------- 2: degree by src, edge count by dst --------------------------
__global__ void k_degcnt(const int* __restrict__ ei,
                         const float* __restrict__ ew) {
    int e = blockIdx.x * blockDim.x + threadIdx.x;
    if (e >= EE) return;
    int s = ei[e];
    int d = ei[EE + e];
    atomicAdd(&g_deg[s], ew[e]);
    atomicAdd(&g_cnt[d], 1);
}

// ---------------- 3: dinv = deg>0 ? rsqrt(deg) : 0 -----------------------------
__global__ void k_dinv() {
    int i = blockIdx.x * blockDim.x + threadIdx.x;
    if (i >= NN) return;
    float dg = g_deg[i];
    g_dinv[i] = (dg > 0.f) ? rsqrtf(dg) : 0.f;
}

// ---------------- 4: multi-block chained exclusive scan -> rowptr --------------
// 13 blocks x 256 threads x 16 elems. Also zeroes g_cnt for reuse as cursor.
__global__ void k_scan_chain() {
    __shared__ int s_wsum[8];
    __shared__ int s_prev;
    int tid = threadIdx.x, b = blockIdx.x;
    int lane = tid & 31, w = tid >> 5;
    int base = b * 4096 + tid * 16;
    int v[16];
    int run = 0;
    #pragma unroll
    for (int j = 0; j < 16; j++) {
        int i = base + j;
        int c = 0;
        if (i < NN) { c = g_cnt[i]; g_cnt[i] = 0; }
        run += c;
        v[j] = run;   // inclusive within thread
    }
    int sc = run;
    #pragma unroll
    for (int off = 1; off < 32; off <<= 1) {
        int t2 = __shfl_up_sync(0xffffffffu, sc, off);
        if (lane >= off) sc += t2;
    }
    if (lane == 31) s_wsum[w] = sc;
    __syncthreads();
    if (w == 0) {
        int xv = (lane < 8) ? s_wsum[lane] : 0;
        #pragma unroll
        for (int off = 1; off < 8; off <<= 1) {
            int t2 = __shfl_up_sync(0xffffffffu, xv, off);
            if (lane >= off) xv += t2;
        }
        if (lane < 8) s_wsum[lane] = xv;
    }
    __syncthreads();
    int thread_excl = sc - run + (w ? s_wsum[w - 1] : 0);
    int block_total = s_wsum[7];
    if (tid == 0) {
        int prev = 0;
        if (b > 0) {
            while (((volatile int*)g_scan_flag)[b - 1] == 0) { }
            __threadfence();
            prev = g_scan_val[b - 1];
        }
        g_scan_val[b] = prev + block_total;
        __threadfence();
        ((volatile int*)g_scan_flag)[b] = 1;
        s_prev = prev;
    }
    __syncthreads();
    int off0 = s_prev + thread_excl;
    #pragma unroll
    for (int j = 0; j < 16; j++) {
        int i = base + j;
        if (i < NN) g_rowptr[i + 1] = off0 + v[j];
    }
    if (b == 0 && tid == 0) g_rowptr[0] = 0;
}

// ---------------- 5: CSR fill (edges grouped by dst), packed (src,w) -----------
__global__ void k_fill(const int* __restrict__ ei,
                       const float* __restrict__ ew) {
    int e = blockIdx.x * blockDim.x + threadIdx.x;
    if (e >= EE) return;
    int s = ei[e];
    int d = ei[EE + e];
    float nv = -g_dinv[s] * ew[e] * g_dinv[d];
    int idx = g_rowptr[d] + atomicAdd(&g_cnt[d], 1);
    g_edge[idx] = make_uint2((unsigned)s, __float_as_uint(nv));
}

// ---------------- 6: SpMM (fp16 gather, fp32 accumulate) -----------------------
// One warp per dst row; lane owns 8 contiguous halves (16B = 1 uint4).
// MODE 0: g_xh -> g_t1h.   MODE 1: g_t1h -> g_t2h.
// Device globals referenced ONLY from device code (never passed from host!).
template <int MODE>
__global__ void k_spmm_h() {
    int row = (blockIdx.x * blockDim.x + threadIdx.x) >> 5;
    int lane = threadIdx.x & 31;
    if (row >= NN) return;
    int e = g_rowptr[row];
    int end = g_rowptr[row + 1];

    const uint4* __restrict__ vin =
        (MODE == 0) ? (const uint4*)g_xh : (const uint4*)g_t1h;
    uint4* __restrict__ vout =
        (MODE == 0) ? (uint4*)g_t1h : (uint4*)g_t2h;

    float acc[8] = {0.f, 0.f, 0.f, 0.f, 0.f, 0.f, 0.f, 0.f};

    #pragma unroll 1
    while (e + 2 <= end) {
        uint2 e0 = g_edge[e], e1 = g_edge[e + 1];
        uint4 v0 = vin[(size_t)e0.x * 32 + lane];
        uint4 v1 = vin[(size_t)e1.x * 32 + lane];
        float w0 = __uint_as_float(e0.y), w1 = __uint_as_float(e1.y);
        {
            float2 f0 = __half22float2(*(const __half2*)&v0.x);
            float2 f1 = __half22float2(*(const __half2*)&v0.y);
            float2 f2 = __half22float2(*(const __half2*)&v0.z);
            float2 f3 = __half22float2(*(const __half2*)&v0.w);
            acc[0] += w0 * f0.x; acc[1] += w0 * f0.y;
            acc[2] += w0 * f1.x; acc[3] += w0 * f1.y;
            acc[4] += w0 * f2.x; acc[5] += w0 * f2.y;
            acc[6] += w0 * f3.x; acc[7] += w0 * f3.y;
        }
        {
            float2 f0 = __half22float2(*(const __half2*)&v1.x);
            float2 f1 = __half22float2(*(const __half2*)&v1.y);
            float2 f2 = __half22float2(*(const __half2*)&v1.z);
            float2 f3 = __half22float2(*(const __half2*)&v1.w);
            acc[0] += w1 * f0.x; acc[1] += w1 * f0.y;
            acc[2] += w1 * f1.x; acc[3] += w1 * f1.y;
            acc[4] += w1 * f2.x; acc[5] += w1 * f2.y;
            acc[6] += w1 * f3.x; acc[7] += w1 * f3.y;
        }
        e += 2;
    }
    if (e < end) {
        uint2 e0 = g_edge[e];
        uint4 v0 = vin[(size_t)e0.x * 32 + lane];
        float w0 = __uint_as_float(e0.y);
        float2 f0 = __half22float2(*(const __half2*)&v0.x);
        float2 f1 = __half22float2(*(const __half2*)&v0.y);
        float2 f2 = __half22float2(*(const __half2*)&v0.z);
        float2 f3 = __half22float2(*(const __half2*)&v0.w);
        acc[0] += w0 * f0.x; acc[1] += w0 * f0.y;
        acc[2] += w0 * f1.x; acc[3] += w0 * f1.y;
        acc[4] += w0 * f2.x; acc[5] += w0 * f2.y;
        acc[6] += w0 * f3.x; acc[7] += w0 * f3.y;
    }

    uint4 o;
    *(__half2*)&o.x = __floats2half2_rn(acc[0], acc[1]);
    *(__half2*)&o.y = __floats2half2_rn(acc[2], acc[3]);
    *(__half2*)&o.z = __floats2half2_rn(acc[4], acc[5]);
    *(__half2*)&o.w = __floats2half2_rn(acc[6], acc[7]);
    vout[(size_t)row * 32 + lane] = o;
}

// ---------------- 7: combine (Cheb matvecs + bias, FFMA2) + BN partials --------
// One thread per (n, m) row. T2 = 2*t2raw - x computed inline (x exact fp32).
__global__ void k_combine(const float* __restrict__ x,
                          const float* __restrict__ W,
                          const float* __restrict__ bias) {
    __shared__ __align__(16) float sW[3 * CC * OO + OO];  // W0,W1,W2 + bias
    __shared__ float sSum[MM][OO];
    __shared__ float sSq[MM][OO];

    for (int i = threadIdx.x; i < 3 * CC * OO + OO; i += blockDim.x)
        sW[i] = (i < 3 * CC * OO) ? W[i] : bias[i - 3 * CC * OO];
    {
        int mi = threadIdx.x >> 5, oi = threadIdx.x & 31;
        sSum[mi][oi] = 0.f;
        sSq[mi][oi] = 0.f;
    }
    __syncthreads();

    int t = blockIdx.x * blockDim.x + threadIdx.x;
    int m = t & 7;
    bool active = (t < NN * MM);

    if (active) {
        int n = t >> 3;
        // exact fp32 x for T0 and the (2*t2 - x) correction
        float xv[CC];
        {
            const float4* xp = (const float4*)&x[((size_t)m * NN + n) * CC];
            #pragma unroll
            for (int q = 0; q < 8; q++) {
                float4 v = xp[q];
                xv[q * 4 + 0] = v.x; xv[q * 4 + 1] = v.y;
                xv[q * 4 + 2] = v.z; xv[q * 4 + 3] = v.w;
            }
        }
        // t1 / t2: 32 halves each = 4 x uint4 (8 halves per uint4)
        float t1f[CC], t2f[CC];
        {
            const uint4* p1 = (const uint4*)&g_t1h[(size_t)n * FF + m * CC];
            const uint4* p2 = (const uint4*)&g_t2h[(size_t)n * FF + m * CC];
            #pragma unroll
            for (int q = 0; q < 4; q++) {
                uint4 u1 = p1[q], u2 = p2[q];
                const __half2* h1 = (const __half2*)&u1;
                const __half2* h2 = (const __half2*)&u2;
                #pragma unroll
                for (int j = 0; j < 4; j++) {
                    float2 f1 = __half22float2(h1[j]);
                    float2 f2 = __half22float2(h2[j]);
                    t1f[q * 8 + j * 2 + 0] = f1.x;
                    t1f[q * 8 + j * 2 + 1] = f1.y;
                    t2f[q * 8 + j * 2 + 0] = f2.x;
                    t2f[q * 8 + j * 2 + 1] = f2.y;
                }
            }
        }

        // packed f32x2 accumulators (native u64 regs; no float aliasing)
        unsigned long long acc2[16];
        #pragma unroll
        for (int o = 0; o < 16; o++)
            acc2[o] = pk2two(sW[3 * CC * OO + o * 2], sW[3 * CC * OO + o * 2 + 1]);

        #pragma unroll
        for (int c = 0; c < CC; c++) {
            float a = xv[c];
            float b = t1f[c];
            float c2 = 2.f * t2f[c] - a;
            unsigned long long a2 = pk2(a), b2 = pk2(b), cc2 = pk2(c2);
            const ulonglong2* w0 = (const ulonglong2*)&sW[c * OO];
            const ulonglong2* w1 = (const ulonglong2*)&sW[CC * OO + c * OO];
            const ulonglong2* w2 = (const ulonglong2*)&sW[2 * CC * OO + c * OO];
            #pragma unroll
            for (int o = 0; o < 8; o++) {
                ulonglong2 u0 = w0[o], u1 = w1[o], u2 = w2[o];
                ffma2(acc2[2 * o],     a2,  u0.x);
                ffma2(acc2[2 * o + 1], a2,  u0.y);
                ffma2(acc2[2 * o],     b2,  u1.x);
                ffma2(acc2[2 * o + 1], b2,  u1.y);
                ffma2(acc2[2 * o],     cc2, u2.x);
                ffma2(acc2[2 * o + 1], cc2, u2.y);
            }
        }

        // unpack, store, BN partials
        float accf[OO];
        #pragma unroll
        for (int o = 0; o < 16; o++)
            unpk2(accf[o * 2], accf[o * 2 + 1], acc2[o]);

        float4* op = (float4*)&g_outpre[(size_t)n * FF + m * CC];
        #pragma unroll
        for (int o = 0; o < 8; o++)
            op[o] = make_float4(accf[o * 4 + 0], accf[o * 4 + 1],
                                accf[o * 4 + 2], accf[o * 4 + 3]);

        #pragma unroll
        for (int o = 0; o < OO; o++) {
            atomicAdd(&sSum[m][o], accf[o]);
            atomicAdd(&sSq[m][o], accf[o] * accf[o]);
        }
    }
    __syncthreads();
    {
        int mi = threadIdx.x >> 5, oi = threadIdx.x & 31;
        atomicAdd(&g_bnsum[threadIdx.x], sSum[mi][oi]);
        atomicAdd(&g_bnsq[threadIdx.x], sSq[mi][oi]);
    }
}

// ---------------- 8: finalize BN stats -> scale/shift --------------------------
__global__ void k_finalize(const float* __restrict__ gamma,
                           const float* __restrict__ beta) {
    int i = threadIdx.x;  // 0..255 = (m, o)
    if (i >= MM * OO) return;
    int o = i & 31;
    float mean = g_bnsum[i] * (1.f / NN);
    float var = g_bnsq[i] * (1.f / NN) - mean * mean;
    float sc = gamma[o] * rsqrtf(var + BN_EPS);
    g_scale[i] = sc;
    g_shift[i] = beta[o] - mean * sc;
}

// ---------------- 9: normalize + relu + transpose to [B,T,N,O] -----------------
__global__ void k_output(float* __restrict__ out) {
    int t = blockIdx.x * blockDim.x + threadIdx.x;
    if (t >= NN * MM * 8) return;
    int o4 = t & 7;
    int nm = t >> 3;
    int n = nm % NN;
    int m = nm / NN;
    float4 v = *(const float4*)&g_outpre[((size_t)n * MM + m) * CC + o4 * 4];
    int si = m * OO + o4 * 4;
    float4 r;
    r.x = fmaxf(0.f, v.x * g_scale[si + 0] + g_shift[si + 0]);
    r.y = fmaxf(0.f, v.y * g_scale[si + 1] + g_shift[si + 1]);
    r.z = fmaxf(0.f, v.z * g_scale[si + 2] + g_shift[si + 2]);
    r.w = fmaxf(0.f, v.w * g_scale[si + 3] + g_shift[si + 3]);
    ((float4*)out)[t] = r;
}

// ------------------------------------------------------------------------------
extern "C" void kernel_launch(void* const* d_in, const int* in_sizes, int n_in,
                              void* d_out, int out_size) {
    const float* x      = (const float*)d_in[0];
    const int*   ei     = (const int*)d_in[1];
    const float* ew     = (const float*)d_in[2];
    const float* W      = (const float*)d_in[3];
    const float* bias   = (const float*)d_in[4];
    const float* gamma  = (const float*)d_in[5];
    const float* beta   = (const float*)d_in[6];
    float* out          = (float*)d_out;

    k_zero<<<(NN + 255) / 256, 256>>>();
    k_xconv<<<(NN * MM * 16 + 255) / 256, 256>>>(x);
    k_degcnt<<<(EE + 255) / 256, 256>>>(ei, ew);
    k_dinv<<<(NN + 255) / 256, 256>>>();
    k_scan_chain<<<SCAN_NBLK, 256>>>();
    k_fill<<<(EE + 255) / 256, 256>>>(ei, ew);
    k_spmm_h<0><<<(NN * 32 + 255) / 256, 256>>>();   // g_xh  -> g_t1h (Lx)
    k_spmm_h<1><<<(NN * 32 + 255) / 256, 256>>>();   // g_t1h -> g_t2h (L(Lx))
    k_combine<<<(NN * MM + 255) / 256, 256>>>(x, W, bias);
    k_finalize<<<1, 256>>>(gamma, beta);
    k_output<<<(NN * MM * 8 + 255) / 256, 256>>>(out);
}

// round 7
// speedup vs baseline: 2.0211x; 1.7888x over previous
#include <cuda_runtime.h>
#include <cuda_fp16.h>
#include <stdint.h>

// Problem constants (fixed shapes for this problem instance)
#define NN 50000       // nodes
#define EE 800000      // edges
#define MM 8           // B*T
#define CC 32          // in channels
#define OO 32          // out channels
#define FF 256         // MM*CC features per node
#define BN_EPS 1e-5f
#define SCAN_NBLK 13   // ceil(NN / 4096)

// ---------------- scratch (device globals; no allocation allowed) -------------
__device__ float g_deg[NN];
__device__ float g_dinv[NN];
__device__ int   g_cnt[NN];          // histogram by dst, reused as fill cursor
__device__ int   g_rowptr[NN + 1];
__device__ __align__(16) uint2 g_edge[EE];              // (src, bitcast weight)
__device__ __align__(16) __half g_xh[(size_t)NN * FF];  // x, node-major fp16
__device__ __align__(16) __half g_t1h[(size_t)NN * FF]; // L x (fp16)
__device__ __align__(16) __half g_t2h[(size_t)NN * FF]; // L(Lx) raw (fp16)
__device__ __align__(16) float g_outpre[(size_t)NN * FF]; // pre-BN [n][m][o]
__device__ float g_bnsum[MM * OO];
__device__ float g_bnsq[MM * OO];
__device__ float g_scale[MM * OO];
__device__ float g_shift[MM * OO];
__device__ int   g_scan_val[SCAN_NBLK];
__device__ int   g_scan_flag[SCAN_NBLK];

// ---------------- packed f32x2 helpers ----------------------------------------
__device__ __forceinline__ unsigned long long pk2(float v) {
    unsigned long long r;
    asm("mov.b64 %0, {%1, %2};" : "=l"(r) : "f"(v), "f"(v));
    return r;
}
__device__ __forceinline__ unsigned long long pk2two(float lo, float hi) {
    unsigned long long r;
    asm("mov.b64 %0, {%1, %2};" : "=l"(r) : "f"(lo), "f"(hi));
    return r;
}
__device__ __forceinline__ void unpk2(float& lo, float& hi, unsigned long long v) {
    asm("mov.b64 {%0, %1}, %2;" : "=f"(lo), "=f"(hi) : "l"(v));
}
__device__ __forceinline__ void ffma2(unsigned long long& d,
                                      unsigned long long a,
                                      unsigned long long b) {
    asm("fma.rn.f32x2 %0, %1, %2, %0;" : "+l"(d) : "l"(a), "l"(b));
}

// ---------------- 0: zero degree / counts / BN sums / scan flags ---------------
__global__ void k_zero() {
    int i = blockIdx.x * blockDim.x + threadIdx.x;
    if (i < NN) { g_deg[i] = 0.f; g_cnt[i] = 0; }
    if (i < MM * OO) { g_bnsum[i] = 0.f; g_bnsq[i] = 0.f; }
    if (i < SCAN_NBLK) g_scan_flag[i] = 0;
}

// ---------------- 1: degree by src, edge count by dst --------------------------
__global__ void k_degcnt(const int* __restrict__ ei,
                         const float* __restrict__ ew) {
    int e = blockIdx.x * blockDim.x + threadIdx.x;
    if (e >= EE) return;
    int s = ei[e];
    int d = ei[EE + e];
    atomicAdd(&g_deg[s], ew[e]);
    atomicAdd(&g_cnt[d], 1);
}

// ---------------- 2: scan(cnt)->rowptr  +  dinv (fused) ------------------------
// 13 blocks x 256 threads x 16 elems, chained decoupled-lookback style.
// Also zeroes g_cnt for reuse as fill cursor and computes g_dinv.
__global__ void k_scan_dinv() {
    __shared__ int s_wsum[8];
    __shared__ int s_prev;
    int tid = threadIdx.x, b = blockIdx.x;
    int lane = tid & 31, w = tid >> 5;

    // fused dinv over this block's node range
    for (int i = b * 4096 + tid; i < (b + 1) * 4096 && i < NN; i += 256) {
        float dg = g_deg[i];
        g_dinv[i] = (dg > 0.f) ? rsqrtf(dg) : 0.f;
    }

    int base = b * 4096 + tid * 16;
    int v[16];
    int run = 0;
    #pragma unroll
    for (int j = 0; j < 16; j++) {
        int i = base + j;
        int c = 0;
        if (i < NN) { c = g_cnt[i]; g_cnt[i] = 0; }
        run += c;
        v[j] = run;   // inclusive within thread
    }
    int sc = run;
    #pragma unroll
    for (int off = 1; off < 32; off <<= 1) {
        int t2 = __shfl_up_sync(0xffffffffu, sc, off);
        if (lane >= off) sc += t2;
    }
    if (lane == 31) s_wsum[w] = sc;
    __syncthreads();
    if (w == 0) {
        int xv = (lane < 8) ? s_wsum[lane] : 0;
        #pragma unroll
        for (int off = 1; off < 8; off <<= 1) {
            int t2 = __shfl_up_sync(0xffffffffu, xv, off);
            if (lane >= off) xv += t2;
        }
        if (lane < 8) s_wsum[lane] = xv;
    }
    __syncthreads();
    int thread_excl = sc - run + (w ? s_wsum[w - 1] : 0);
    int block_total = s_wsum[7];
    if (tid == 0) {
        int prev = 0;
        if (b > 0) {
            while (((volatile int*)g_scan_flag)[b - 1] == 0) { }
            __threadfence();
            prev = g_scan_val[b - 1];
        }
        g_scan_val[b] = prev + block_total;
        __threadfence();
        ((volatile int*)g_scan_flag)[b] = 1;
        s_prev = prev;
    }
    __syncthreads();
    int off0 = s_prev + thread_excl;
    #pragma unroll
    for (int j = 0; j < 16; j++) {
        int i = base + j;
        if (i < NN) g_rowptr[i + 1] = off0 + v[j];
    }
    if (b == 0 && tid == 0) g_rowptr[0] = 0;
}

// ---------------- 3: CSR fill (edges grouped by dst), packed (src,w) -----------
__global__ void k_fill(const int* __restrict__ ei,
                       const float* __restrict__ ew) {
    int e = blockIdx.x * blockDim.x + threadIdx.x;
    if (e >= EE) return;
    int s = ei[e];
    int d = ei[EE + e];
    float nv = -g_dinv[s] * ew[e] * g_dinv[d];
    int idx = g_rowptr[d] + atomicAdd(&g_cnt[d], 1);
    g_edge[idx] = make_uint2((unsigned)s, __float_as_uint(nv));
}

// ---------------- 4: x -> node-major fp16 [n][m*32+c] --------------------------
__global__ void k_xconv(const float* __restrict__ x) {
    int t = blockIdx.x * blockDim.x + threadIdx.x;
    if (t >= NN * MM * 16) return;
    int c2 = t & 15;
    int m = (t >> 4) & 7;
    int n = t >> 7;
    float2 v = *(const float2*)&x[((size_t)m * NN + n) * CC + c2 * 2];
    *(__half2*)&g_xh[(size_t)n * FF + m * CC + c2 * 2] = __floats2half2_rn(v.x, v.y);
}

// ---------------- 5: SpMM (fp16 gather, fp32 accumulate), unroll-4 -------------
// One warp per dst row; lane owns 8 contiguous halves (16B = 1 uint4).
// MODE 0: g_xh -> g_t1h.   MODE 1: g_t1h -> g_t2h.
__device__ __forceinline__ void acc_edge(float* acc, uint4 v, float w) {
    float2 f0 = __half22float2(*(const __half2*)&v.x);
    float2 f1 = __half22float2(*(const __half2*)&v.y);
    float2 f2 = __half22float2(*(const __half2*)&v.z);
    float2 f3 = __half22float2(*(const __half2*)&v.w);
    acc[0] += w * f0.x; acc[1] += w * f0.y;
    acc[2] += w * f1.x; acc[3] += w * f1.y;
    acc[4] += w * f2.x; acc[5] += w * f2.y;
    acc[6] += w * f3.x; acc[7] += w * f3.y;
}

template <int MODE>
__global__ void k_spmm_h() {
    int row = (blockIdx.x * blockDim.x + threadIdx.x) >> 5;
    int lane = threadIdx.x & 31;
    if (row >= NN) return;
    int e = g_rowptr[row];
    int end = g_rowptr[row + 1];

    const uint4* __restrict__ vin =
        (MODE == 0) ? (const uint4*)g_xh : (const uint4*)g_t1h;
    uint4* __restrict__ vout =
        (MODE == 0) ? (uint4*)g_t1h : (uint4*)g_t2h;

    float acc[8] = {0.f, 0.f, 0.f, 0.f, 0.f, 0.f, 0.f, 0.f};

    #pragma unroll 1
    while (e + 4 <= end) {
        uint2 E0 = g_edge[e], E1 = g_edge[e + 1];
        uint2 E2 = g_edge[e + 2], E3 = g_edge[e + 3];
        uint4 V0 = vin[(size_t)E0.x * 32 + lane];
        uint4 V1 = vin[(size_t)E1.x * 32 + lane];
        uint4 V2 = vin[(size_t)E2.x * 32 + lane];
        uint4 V3 = vin[(size_t)E3.x * 32 + lane];
        acc_edge(acc, V0, __uint_as_float(E0.y));
        acc_edge(acc, V1, __uint_as_float(E1.y));
        acc_edge(acc, V2, __uint_as_float(E2.y));
        acc_edge(acc, V3, __uint_as_float(E3.y));
        e += 4;
    }
    #pragma unroll 1
    while (e < end) {
        uint2 E0 = g_edge[e];
        uint4 V0 = vin[(size_t)E0.x * 32 + lane];
        acc_edge(acc, V0, __uint_as_float(E0.y));
        e++;
    }

    uint4 o;
    *(__half2*)&o.x = __floats2half2_rn(acc[0], acc[1]);
    *(__half2*)&o.y = __floats2half2_rn(acc[2], acc[3]);
    *(__half2*)&o.z = __floats2half2_rn(acc[4], acc[5]);
    *(__half2*)&o.w = __floats2half2_rn(acc[6], acc[7]);
    vout[(size_t)row * 32 + lane] = o;
}

// ---------------- 6: combine (Cheb matvecs + bias, FFMA2), NO atomics ----------
// One thread per (n, m) row, streaming 8-channel chunks to keep regs low.
__global__ void k_combine(const float* __restrict__ x,
                          const float* __restrict__ W,
                          const float* __restrict__ bias) {
    __shared__ __align__(16) float sW[3 * CC * OO + OO];  // W0,W1,W2 + bias

    for (int i = threadIdx.x; i < 3 * CC * OO + OO; i += blockDim.x)
        sW[i] = (i < 3 * CC * OO) ? W[i] : bias[i - 3 * CC * OO];
    __syncthreads();

    int t = blockIdx.x * blockDim.x + threadIdx.x;
    if (t >= NN * MM) return;
    int m = t & 7;
    int n = t >> 3;

    const float4* xp = (const float4*)&x[((size_t)m * NN + n) * CC];
    const uint4* p1 = (const uint4*)&g_t1h[(size_t)n * FF + m * CC];
    const uint4* p2 = (const uint4*)&g_t2h[(size_t)n * FF + m * CC];

    // packed f32x2 accumulators (32 outputs in 16 u64 regs), init with bias
    unsigned long long acc2[16];
    #pragma unroll
    for (int o = 0; o < 16; o++)
        acc2[o] = pk2two(sW[3 * CC * OO + o * 2], sW[3 * CC * OO + o * 2 + 1]);

    #pragma unroll
    for (int q = 0; q < 4; q++) {          // 8 channels per chunk
        float4 xa = xp[q * 2], xb = xp[q * 2 + 1];
        uint4 u1 = p1[q], u2 = p2[q];
        float xs[8] = {xa.x, xa.y, xa.z, xa.w, xb.x, xb.y, xb.z, xb.w};
        float t1s[8], t2s[8];
        {
            const __half2* h1 = (const __half2*)&u1;
            const __half2* h2 = (const __half2*)&u2;
            #pragma unroll
            for (int j = 0; j < 4; j++) {
                float2 f1 = __half22float2(h1[j]);
                float2 f2 = __half22float2(h2[j]);
                t1s[j * 2] = f1.x; t1s[j * 2 + 1] = f1.y;
                t2s[j * 2] = f2.x; t2s[j * 2 + 1] = f2.y;
            }
        }
        #pragma unroll
        for (int j = 0; j < 8; j++) {
            int c = q * 8 + j;
            float a = xs[j];
            float b = t1s[j];
            float c2 = 2.f * t2s[j] - a;
            unsigned long long a2 = pk2(a), b2 = pk2(b), cc2 = pk2(c2);
            const ulonglong2* w0 = (const ulonglong2*)&sW[c * OO];
            const ulonglong2* w1 = (const ulonglong2*)&sW[CC * OO + c * OO];
            const ulonglong2* w2 = (const ulonglong2*)&sW[2 * CC * OO + c * OO];
            #pragma unroll
            for (int o = 0; o < 8; o++) {
                ulonglong2 u0 = w0[o], u1w = w1[o], u2w = w2[o];
                ffma2(acc2[2 * o],     a2,  u0.x);
                ffma2(acc2[2 * o + 1], a2,  u0.y);
                ffma2(acc2[2 * o],     b2,  u1w.x);
                ffma2(acc2[2 * o + 1], b2,  u1w.y);
                ffma2(acc2[2 * o],     cc2, u2w.x);
                ffma2(acc2[2 * o + 1], cc2, u2w.y);
            }
        }
    }

    float4* op = (float4*)&g_outpre[(size_t)n * FF + m * CC];
    #pragma unroll
    for (int o = 0; o < 8; o++) {
        float r0, r1, r2, r3;
        unpk2(r0, r1, acc2[o * 2]);
        unpk2(r2, r3, acc2[o * 2 + 1]);
        op[o] = make_float4(r0, r1, r2, r3);
    }
}

// ---------------- 7: BN statistics (streaming, coalesced) ----------------------
// Block b covers n in [b*256, b*256+256); thread tid owns (m,o) = tid.
__global__ void k_stats() {
    int tid = threadIdx.x;
    int nbase = blockIdx.x * 256;
    int rows = NN - nbase; if (rows > 256) rows = 256;
    float s = 0.f, sq = 0.f;
    const float* p = &g_outpre[(size_t)nbase * FF + tid];
    #pragma unroll 4
    for (int r = 0; r < rows; r++) {
        float v = p[(size_t)r * FF];
        s += v; sq += v * v;
    }
    atomicAdd(&g_bnsum[tid], s);
    atomicAdd(&g_bnsq[tid], sq);
}

// ---------------- 8: finalize BN stats -> scale/shift --------------------------
__global__ void k_finalize(const float* __restrict__ gamma,
                           const float* __restrict__ beta) {
    int i = threadIdx.x;  // 0..255 = (m, o)
    if (i >= MM * OO) return;
    int o = i & 31;
    float mean = g_bnsum[i] * (1.f / NN);
    float var = g_bnsq[i] * (1.f / NN) - mean * mean;
    float sc = gamma[o] * rsqrtf(var + BN_EPS);
    g_scale[i] = sc;
    g_shift[i] = beta[o] - mean * sc;
}

// ---------------- 9: normalize + relu + transpose via shared tile ---------------
// Block handles 32 n-rows: load [32][256] coalesced, write [m][n][o] coalesced.
#define TN 32
#define SHF4 65   // padded row stride in float4 (64 data + 1 pad)
__global__ void k_output(float* __restrict__ out) {
    __shared__ __align__(16) float4 sh[TN * SHF4];
    __shared__ float ssc[MM * OO], ssh[MM * OO];
    int tid = threadIdx.x;
    int nbase = blockIdx.x * TN;
    int nmax = NN - nbase; if (nmax > TN) nmax = TN;

    ssc[tid] = g_scale[tid];
    ssh[tid] = g_shift[tid];

    const float4* src = (const float4*)&g_outpre[(size_t)nbase * FF];
    for (int i = tid; i < nmax * 64; i += 256) {
        int nl = i >> 6, j = i & 63;
        sh[nl * SHF4 + j] = src[i];
    }
    __syncthreads();

    // write loop: i = m*256 + nl*8 + o4 (full tile); guard nl < nmax
    for (int i = tid; i < MM * TN * 8; i += 256) {
        int m = i >> 8;
        int nl = (i >> 3) & 31;
        int o4 = i & 7;
        if (nl >= nmax) continue;
        float4 v = sh[nl * SHF4 + m * 8 + o4];
        int si = m * OO + o4 * 4;
        float4 r;
        r.x = fmaxf(0.f, v.x * ssc[si + 0] + ssh[si + 0]);
        r.y = fmaxf(0.f, v.y * ssc[si + 1] + ssh[si + 1]);
        r.z = fmaxf(0.f, v.z * ssc[si + 2] + ssh[si + 2]);
        r.w = fmaxf(0.f, v.w * ssc[si + 3] + ssh[si + 3]);
        ((float4*)out)[((size_t)m * NN + nbase + nl) * 8 + o4] = r;
    }
}

// ------------------------------------------------------------------------------
extern "C" void kernel_launch(void* const* d_in, const int* in_sizes, int n_in,
                              void* d_out, int out_size) {
    const float* x      = (const float*)d_in[0];
    const int*   ei     = (const int*)d_in[1];
    const float* ew     = (const float*)d_in[2];
    const float* W      = (const float*)d_in[3];
    const float* bias   = (const float*)d_in[4];
    const float* gamma  = (const float*)d_in[5];
    const float* beta   = (const float*)d_in[6];
    float* out          = (float*)d_out;

    k_zero<<<(NN + 255) / 256, 256>>>();                    // 1
    k_degcnt<<<(EE + 255) / 256, 256>>>(ei, ew);            // 2
    k_scan_dinv<<<SCAN_NBLK, 256>>>();                      // 3
    k_fill<<<(EE + 255) / 256, 256>>>(ei, ew);              // 4  <- profiled slot
    k_xconv<<<(NN * MM * 16 + 255) / 256, 256>>>(x);        // 5
    k_spmm_h<0><<<(NN * 32 + 255) / 256, 256>>>();          // 6: g_xh  -> g_t1h
    k_spmm_h<1><<<(NN * 32 + 255) / 256, 256>>>();          // 7: g_t1h -> g_t2h
    k_combine<<<(NN * MM + 255) / 256, 256>>>(x, W, bias);  // 8
    k_stats<<<(NN + 255) / 256, 256>>>();                   // 9
    k_finalize<<<1, 256>>>(gamma, beta);                    // 10
    k_output<<<(NN + TN - 1) / TN, 256>>>(out);             // 11
}

// round 9
// speedup vs baseline: 2.2552x; 1.1159x over previous
#include <cuda_runtime.h>
#include <cuda_fp16.h>
#include <stdint.h>

// Problem constants (fixed shapes for this problem instance)
#define NN 50000       // nodes
#define EE 800000      // edges
#define MM 8           // B*T
#define CC 32          // in channels
#define OO 32          // out channels
#define FF 256         // MM*CC features per node
#define BN_EPS 1e-5f
#define SCAN_NBLK 13   // ceil(NN / 4096)

// ---------------- scratch (device globals; no allocation allowed) -------------
// NOTE: launch order relies on these being zero at entry. First call uses the
// CUDA static zero-initialization; k_cleanup (last launch) re-zeroes the
// accumulated ones so every graph replay starts from identical state.
__device__ float g_deg[NN];
__device__ float g_dinv[NN];
__device__ int   g_cnt[NN];          // histogram by dst, reused as fill cursor
__device__ int   g_rowptr[NN + 1];
__device__ __align__(16) uint2 g_edge[EE];              // (src, bitcast weight)
__device__ __align__(16) __half g_xh[(size_t)NN * FF];  // x, node-major fp16
__device__ __align__(16) __half g_t1h[(size_t)NN * FF]; // L x (fp16)
__device__ __align__(16) __half g_t2h[(size_t)NN * FF]; // L(Lx) raw (fp16)
__device__ __align__(16) float g_outpre[(size_t)NN * FF]; // pre-BN [n][m][o]
__device__ float g_bnsum[MM * OO];
__device__ float g_bnsq[MM * OO];
__device__ float g_scale[MM * OO];
__device__ float g_shift[MM * OO];
__device__ int   g_scan_val[SCAN_NBLK];
__device__ int   g_scan_flag[SCAN_NBLK];

// ---------------- packed f32x2 helpers ----------------------------------------
__device__ __forceinline__ unsigned long long pk2(float v) {
    unsigned long long r;
    asm("mov.b64 %0, {%1, %2};" : "=l"(r) : "f"(v), "f"(v));
    return r;
}
__device__ __forceinline__ unsigned long long pk2two(float lo, float hi) {
    unsigned long long r;
    asm("mov.b64 %0, {%1, %2};" : "=l"(r) : "f"(lo), "f"(hi));
    return r;
}
__device__ __forceinline__ void unpk2(float& lo, float& hi, unsigned long long v) {
    asm("mov.b64 {%0, %1}, %2;" : "=f"(lo), "=f"(hi) : "l"(v));
}
__device__ __forceinline__ void ffma2(unsigned long long& d,
                                      unsigned long long a,
                                      unsigned long long b) {
    asm("fma.rn.f32x2 %0, %1, %2, %0;" : "+l"(d) : "l"(a), "l"(b));
}

// ---------------- 1: degree/count atomics + x->fp16 conversion (fused) ---------
// Grid covers NN*MM*16 threads for the conversion; first EE threads also
// handle one edge each for the degree/count histograms.
__global__ void k_degcnt_xconv(const float* __restrict__ x,
                               const int* __restrict__ ei,
                               const float* __restrict__ ew) {
    int t = blockIdx.x * blockDim.x + threadIdx.x;
    if (t < EE) {
        int s = ei[t];
        int d = ei[EE + t];
        atomicAdd(&g_deg[s], ew[t]);
        atomicAdd(&g_cnt[d], 1);
    }
    if (t < NN * MM * 16) {
        int c2 = t & 15;
        int m = (t >> 4) & 7;
        int n = t >> 7;
        float2 v = *(const float2*)&x[((size_t)m * NN + n) * CC + c2 * 2];
        *(__half2*)&g_xh[(size_t)n * FF + m * CC + c2 * 2] =
            __floats2half2_rn(v.x, v.y);
    }
}

// ---------------- 2: scan(cnt)->rowptr  +  dinv (fused) ------------------------
__global__ void k_scan_dinv() {
    __shared__ int s_wsum[8];
    __shared__ int s_prev;
    int tid = threadIdx.x, b = blockIdx.x;
    int lane = tid & 31, w = tid >> 5;

    for (int i = b * 4096 + tid; i < (b + 1) * 4096 && i < NN; i += 256) {
        float dg = g_deg[i];
        g_dinv[i] = (dg > 0.f) ? rsqrtf(dg) : 0.f;
    }

    int base = b * 4096 + tid * 16;
    int v[16];
    int run = 0;
    #pragma unroll
    for (int j = 0; j < 16; j++) {
        int i = base + j;
        int c = 0;
        if (i < NN) { c = g_cnt[i]; g_cnt[i] = 0; }
        run += c;
        v[j] = run;   // inclusive within thread
    }
    int sc = run;
    #pragma unroll
    for (int off = 1; off < 32; off <<= 1) {
        int t2 = __shfl_up_sync(0xffffffffu, sc, off);
        if (lane >= off) sc += t2;
    }
    if (lane == 31) s_wsum[w] = sc;
    __syncthreads();
    if (w == 0) {
        int xv = (lane < 8) ? s_wsum[lane] : 0;
        #pragma unroll
        for (int off = 1; off < 8; off <<= 1) {
            int t2 = __shfl_up_sync(0xffffffffu, xv, off);
            if (lane >= off) xv += t2;
        }
        if (lane < 8) s_wsum[lane] = xv;
    }
    __syncthreads();
    int thread_excl = sc - run + (w ? s_wsum[w - 1] : 0);
    int block_total = s_wsum[7];
    if (tid == 0) {
        int prev = 0;
        if (b > 0) {
            while (((volatile int*)g_scan_flag)[b - 1] == 0) { }
            __threadfence();
            prev = g_scan_val[b - 1];
        }
        g_scan_val[b] = prev + block_total;
        __threadfence();
        ((volatile int*)g_scan_flag)[b] = 1;
        s_prev = prev;
    }
    __syncthreads();
    int off0 = s_prev + thread_excl;
    #pragma unroll
    for (int j = 0; j < 16; j++) {
        int i = base + j;
        if (i < NN) g_rowptr[i + 1] = off0 + v[j];
    }
    if (b == 0 && tid == 0) g_rowptr[0] = 0;
}

// ---------------- 3: CSR fill (edges grouped by dst), packed (src,w) -----------
__global__ void k_fill(const int* __restrict__ ei,
                       const float* __restrict__ ew) {
    int e = blockIdx.x * blockDim.x + threadIdx.x;
    if (e >= EE) return;
    int s = ei[e];
    int d = ei[EE + e];
    float nv = -g_dinv[s] * ew[e] * g_dinv[d];
    int idx = g_rowptr[d] + atomicAdd(&g_cnt[d], 1);
    g_edge[idx] = make_uint2((unsigned)s, __float_as_uint(nv));
}

// ---------------- 4/5: SpMM (fp16 gather, fp32 accumulate), unroll-4 -----------
// One warp per dst row; lane owns 8 contiguous halves (16B = 1 uint4).
__device__ __forceinline__ void acc_edge(float* acc, uint4 v, float w) {
    float2 f0 = __half22float2(*(const __half2*)&v.x);
    float2 f1 = __half22float2(*(const __half2*)&v.y);
    float2 f2 = __half22float2(*(const __half2*)&v.z);
    float2 f3 = __half22float2(*(const __half2*)&v.w);
    acc[0] += w * f0.x; acc[1] += w * f0.y;
    acc[2] += w * f1.x; acc[3] += w * f1.y;
    acc[4] += w * f2.x; acc[5] += w * f2.y;
    acc[6] += w * f3.x; acc[7] += w * f3.y;
}

template <int MODE>
__global__ void __launch_bounds__(256) k_spmm_h() {
    int row = (blockIdx.x * blockDim.x + threadIdx.x) >> 5;
    int lane = threadIdx.x & 31;
    if (row >= NN) return;
    int e = g_rowptr[row];
    int end = g_rowptr[row + 1];

    const uint4* __restrict__ vin =
        (MODE == 0) ? (const uint4*)g_xh : (const uint4*)g_t1h;
    uint4* __restrict__ vout =
        (MODE == 0) ? (uint4*)g_t1h : (uint4*)g_t2h;

    float acc[8] = {0.f, 0.f, 0.f, 0.f, 0.f, 0.f, 0.f, 0.f};

    #pragma unroll 1
    while (e + 4 <= end) {
        uint2 E0 = g_edge[e], E1 = g_edge[e + 1];
        uint2 E2 = g_edge[e + 2], E3 = g_edge[e + 3];
        uint4 V0 = vin[(size_t)E0.x * 32 + lane];
        uint4 V1 = vin[(size_t)E1.x * 32 + lane];
        uint4 V2 = vin[(size_t)E2.x * 32 + lane];
        uint4 V3 = vin[(size_t)E3.x * 32 + lane];
        acc_edge(acc, V0, __uint_as_float(E0.y));
        acc_edge(acc, V1, __uint_as_float(E1.y));
        acc_edge(acc, V2, __uint_as_float(E2.y));
        acc_edge(acc, V3, __uint_as_float(E3.y));
        e += 4;
    }
    #pragma unroll 1
    while (e < end) {
        uint2 E0 = g_edge[e];
        uint4 V0 = vin[(size_t)E0.x * 32 + lane];
        acc_edge(acc, V0, __uint_as_float(E0.y));
        e++;
    }

    uint4 o;
    *(__half2*)&o.x = __floats2half2_rn(acc[0], acc[1]);
    *(__half2*)&o.y = __floats2half2_rn(acc[2], acc[3]);
    *(__half2*)&o.z = __floats2half2_rn(acc[4], acc[5]);
    *(__half2*)&o.w = __floats2half2_rn(acc[6], acc[7]);
    vout[(size_t)row * 32 + lane] = o;
}

// ---------------- 6: combine (Cheb matvecs + bias, FFMA2), 2 rows/thread -------
// Thread handles (n0, m) and (n0+1, m): shared-weight loads amortized 2x.
__global__ void __launch_bounds__(256) k_combine(const float* __restrict__ x,
                                                 const float* __restrict__ W,
                                                 const float* __restrict__ bias) {
    __shared__ __align__(16) float sW[3 * CC * OO + OO];  // W0,W1,W2 + bias

    for (int i = threadIdx.x; i < 3 * CC * OO + OO; i += blockDim.x)
        sW[i] = (i < 3 * CC * OO) ? W[i] : bias[i - 3 * CC * OO];
    __syncthreads();

    int t = blockIdx.x * blockDim.x + threadIdx.x;
    if (t >= NN * MM / 2) return;
    int m = t & 7;
    int n0 = (t >> 3) * 2;
    int n1 = n0 + 1;

    const float4* xp0 = (const float4*)&x[((size_t)m * NN + n0) * CC];
    const float4* xp1 = (const float4*)&x[((size_t)m * NN + n1) * CC];
    const uint4* p1a = (const uint4*)&g_t1h[(size_t)n0 * FF + m * CC];
    const uint4* p2a = (const uint4*)&g_t2h[(size_t)n0 * FF + m * CC];
    const uint4* p1b = (const uint4*)&g_t1h[(size_t)n1 * FF + m * CC];
    const uint4* p2b = (const uint4*)&g_t2h[(size_t)n1 * FF + m * CC];

    unsigned long long accA[16], accB[16];
    #pragma unroll
    for (int o = 0; o < 16; o++) {
        unsigned long long bz =
            pk2two(sW[3 * CC * OO + o * 2], sW[3 * CC * OO + o * 2 + 1]);
        accA[o] = bz;
        accB[o] = bz;
    }

    #pragma unroll
    for (int q = 0; q < 4; q++) {          // 8 channels per chunk
        float4 xa0 = xp0[q * 2], xb0 = xp0[q * 2 + 1];
        float4 xa1 = xp1[q * 2], xb1 = xp1[q * 2 + 1];
        uint4 u1a = p1a[q], u2a = p2a[q];
        uint4 u1b = p1b[q], u2b = p2b[q];
        float xs0[8] = {xa0.x, xa0.y, xa0.z, xa0.w, xb0.x, xb0.y, xb0.z, xb0.w};
        float xs1[8] = {xa1.x, xa1.y, xa1.z, xa1.w, xb1.x, xb1.y, xb1.z, xb1.w};
        float t1A[8], t2A[8], t1B[8], t2B[8];
        {
            const __half2* h1a = (const __half2*)&u1a;
            const __half2* h2a = (const __half2*)&u2a;
            const __half2* h1b = (const __half2*)&u1b;
            const __half2* h2b = (const __half2*)&u2b;
            #pragma unroll
            for (int j = 0; j < 4; j++) {
                float2 f1a = __half22float2(h1a[j]);
                float2 f2a = __half22float2(h2a[j]);
                float2 f1b = __half22float2(h1b[j]);
                float2 f2b = __half22float2(h2b[j]);
                t1A[j * 2] = f1a.x; t1A[j * 2 + 1] = f1a.y;
                t2A[j * 2] = f2a.x; t2A[j * 2 + 1] = f2a.y;
                t1B[j * 2] = f1b.x; t1B[j * 2 + 1] = f1b.y;
                t2B[j * 2] = f2b.x; t2B[j * 2 + 1] = f2b.y;
            }
        }
        #pragma unroll
        for (int j = 0; j < 8; j++) {
            int c = q * 8 + j;
            float a0 = xs0[j], b0 = t1A[j], c20 = 2.f * t2A[j] - a0;
            float a1 = xs1[j], b1 = t1B[j], c21 = 2.f * t2B[j] - a1;
            unsigned long long a0p = pk2(a0), b0p = pk2(b0), c0p = pk2(c20);
            unsigned long long a1p = pk2(a1), b1p = pk2(b1), c1p = pk2(c21);
            const ulonglong2* w0 = (const ulonglong2*)&sW[c * OO];
            const ulonglong2* w1 = (const ulonglong2*)&sW[CC * OO + c * OO];
            const ulonglong2* w2 = (const ulonglong2*)&sW[2 * CC * OO + c * OO];
            #pragma unroll
            for (int o = 0; o < 8; o++) {
                ulonglong2 u0 = w0[o], u1w = w1[o], u2w = w2[o];
                ffma2(accA[2 * o],     a0p, u0.x);
                ffma2(accA[2 * o + 1], a0p, u0.y);
                ffma2(accB[2 * o],     a1p, u0.x);
                ffma2(accB[2 * o + 1], a1p, u0.y);
                ffma2(accA[2 * o],     b0p, u1w.x);
                ffma2(accA[2 * o + 1], b0p, u1w.y);
                ffma2(accB[2 * o],     b1p, u1w.x);
                ffma2(accB[2 * o + 1], b1p, u1w.y);
                ffma2(accA[2 * o],     c0p, u2w.x);
                ffma2(accA[2 * o + 1], c0p, u2w.y);
                ffma2(accB[2 * o],     c1p, u2w.x);
                ffma2(accB[2 * o + 1], c1p, u2w.y);
            }
        }
    }

    float4* opA = (float4*)&g_outpre[(size_t)n0 * FF + m * CC];
    float4* opB = (float4*)&g_outpre[(size_t)n1 * FF + m * CC];
    #pragma unroll
    for (int o = 0; o < 8; o++) {
        float r0, r1, r2, r3;
        unpk2(r0, r1, accA[o * 2]);
        unpk2(r2, r3, accA[o * 2 + 1]);
        opA[o] = make_float4(r0, r1, r2, r3);
        unpk2(r0, r1, accB[o * 2]);
        unpk2(r2, r3, accB[o * 2 + 1]);
        opB[o] = make_float4(r0, r1, r2, r3);
    }
}

// ---------------- 7: BN statistics (streaming, coalesced) ----------------------
__global__ void k_stats() {
    int tid = threadIdx.x;
    int nbase = blockIdx.x * 256;
    int rows = NN - nbase; if (rows > 256) rows = 256;
    float s = 0.f, sq = 0.f;
    const float* p = &g_outpre[(size_t)nbase * FF + tid];
    #pragma unroll 4
    for (int r = 0; r < rows; r++) {
        float v = p[(size_t)r * FF];
        s += v; sq += v * v;
    }
    atomicAdd(&g_bnsum[tid], s);
    atomicAdd(&g_bnsq[tid], sq);
}

// ---------------- 8: finalize BN stats -> scale/shift --------------------------
__global__ void k_finalize(const float* __restrict__ gamma,
                           const float* __restrict__ beta) {
    int i = threadIdx.x;  // 0..255 = (m, o)
    if (i >= MM * OO) return;
    int o = i & 31;
    float mean = g_bnsum[i] * (1.f / NN);
    float var = g_bnsq[i] * (1.f / NN) - mean * mean;
    float sc = gamma[o] * rsqrtf(var + BN_EPS);
    g_scale[i] = sc;
    g_shift[i] = beta[o] - mean * sc;
}

// ---------------- 9: normalize + relu + transpose via shared tile ---------------
#define TN 32
#define SHF4 65   // padded row stride in float4 (64 data + 1 pad)
__global__ void k_output(float* __restrict__ out) {
    __shared__ __align__(16) float4 sh[TN * SHF4];
    __shared__ float ssc[MM * OO], ssh[MM * OO];
    int tid = threadIdx.x;
    int nbase = blockIdx.x * TN;
    int nmax = NN - nbase; if (nmax > TN) nmax = TN;

    ssc[tid] = g_scale[tid];
    ssh[tid] = g_shift[tid];

    const float4* src = (const float4*)&g_outpre[(size_t)nbase * FF];
    for (int i = tid; i < nmax * 64; i += 256) {
        int nl = i >> 6, j = i & 63;
        sh[nl * SHF4 + j] = src[i];
    }
    __syncthreads();

    for (int i = tid; i < MM * TN * 8; i += 256) {
        int m = i >> 8;
        int nl = (i >> 3) & 31;
        int o4 = i & 7;
        if (nl >= nmax) continue;
        float4 v = sh[nl * SHF4 + m * 8 + o4];
        int si = m * OO + o4 * 4;
        float4 r;
        r.x = fmaxf(0.f, v.x * ssc[si + 0] + ssh[si + 0]);
        r.y = fmaxf(0.f, v.y * ssc[si + 1] + ssh[si + 1]);
        r.z = fmaxf(0.f, v.z * ssc[si + 2] + ssh[si + 2]);
        r.w = fmaxf(0.f, v.w * ssc[si + 3] + ssh[si + 3]);
        ((float4*)out)[((size_t)m * NN + nbase + nl) * 8 + o4] = r;
    }
}

// ---------------- 10: cleanup -> restore zeroed state for next replay ----------
__global__ void k_cleanup() {
    int i = blockIdx.x * blockDim.x + threadIdx.x;
    if (i < NN) { g_deg[i] = 0.f; g_cnt[i] = 0; }
    if (i < MM * OO) { g_bnsum[i] = 0.f; g_bnsq[i] = 0.f; }
    if (i < SCAN_NBLK) { g_scan_flag[i] = 0; g_scan_val[i] = 0; }
}

// ------------------------------------------------------------------------------
extern "C" void kernel_launch(void* const* d_in, const int* in_sizes, int n_in,
                              void* d_out, int out_size) {
    const float* x      = (const float*)d_in[0];
    const int*   ei     = (const int*)d_in[1];
    const float* ew     = (const float*)d_in[2];
    const float* W      = (const float*)d_in[3];
    const float* bias   = (const float*)d_in[4];
    const float* gamma  = (const float*)d_in[5];
    const float* beta   = (const float*)d_in[6];
    float* out          = (float*)d_out;

    k_degcnt_xconv<<<(NN * MM * 16 + 255) / 256, 256>>>(x, ei, ew);  // 1
    k_scan_dinv<<<SCAN_NBLK, 256>>>();                               // 2
    k_fill<<<(EE + 255) / 256, 256>>>(ei, ew);                       // 3
    k_spmm_h<0><<<(NN * 32 + 255) / 256, 256>>>();                   // 4 <- profiled
    k_spmm_h<1><<<(NN * 32 + 255) / 256, 256>>>();                   // 5
    k_combine<<<(NN * MM / 2 + 255) / 256, 256>>>(x, W, bias);       // 6
    k_stats<<<(NN + 255) / 256, 256>>>();                            // 7
    k_finalize<<<1, 256>>>(gamma, beta);                             // 8
    k_output<<<(NN + TN - 1) / TN, 256>>>(out);                      // 9
    k_cleanup<<<(NN + 255) / 256, 256>>>();                          // 10
}

// round 10
// speedup vs baseline: 2.2972x; 1.0186x over previous
#include <cuda_runtime.h>
#include <cuda_fp16.h>
#include <stdint.h>

// Problem constants (fixed shapes for this problem instance)
#define NN 50000       // nodes
#define EE 800000      // edges
#define MM 8           // B*T
#define CC 32          // in channels
#define OO 32          // out channels
#define FF 256         // MM*CC features per node
#define BN_EPS 1e-5f
#define SCAN_NBLK 13   // ceil(NN / 4096)

// ---------------- scratch (device globals; no allocation allowed) -------------
// NOTE: launch order relies on these being zero at entry. First call uses the
// CUDA static zero-initialization; k_cleanup (last launch) re-zeroes the
// accumulated ones so every graph replay starts from identical state.
__device__ float g_deg[NN];
__device__ float g_dinv[NN];
__device__ int   g_cnt[NN];          // histogram by dst, reused as fill cursor
__device__ int   g_rowptr[NN + 1];
__device__ __align__(16) uint2 g_edge[EE];              // (src, bitcast weight)
__device__ __align__(16) __half g_xh[(size_t)NN * FF];  // x, node-major fp16
__device__ __align__(16) __half g_t1h[(size_t)NN * FF]; // L x (fp16)
__device__ __align__(16) __half g_t2h[(size_t)NN * FF]; // L(Lx) raw (fp16)
__device__ __align__(16) float g_outpre[(size_t)NN * FF]; // pre-BN [n][m][o]
__device__ float g_bnsum[MM * OO];
__device__ float g_bnsq[MM * OO];
__device__ float g_scale[MM * OO];
__device__ float g_shift[MM * OO];
__device__ int   g_scan_val[SCAN_NBLK];
__device__ int   g_scan_flag[SCAN_NBLK];

// ---------------- packed f32x2 helpers ----------------------------------------
__device__ __forceinline__ unsigned long long pk2(float v) {
    unsigned long long r;
    asm("mov.b64 %0, {%1, %2};" : "=l"(r) : "f"(v), "f"(v));
    return r;
}
__device__ __forceinline__ unsigned long long pk2two(float lo, float hi) {
    unsigned long long r;
    asm("mov.b64 %0, {%1, %2};" : "=l"(r) : "f"(lo), "f"(hi));
    return r;
}
__device__ __forceinline__ void unpk2(float& lo, float& hi, unsigned long long v) {
    asm("mov.b64 {%0, %1}, %2;" : "=f"(lo), "=f"(hi) : "l"(v));
}
__device__ __forceinline__ void ffma2(unsigned long long& d,
                                      unsigned long long a,
                                      unsigned long long b) {
    asm("fma.rn.f32x2 %0, %1, %2, %0;" : "+l"(d) : "l"(a), "l"(b));
}

// ---------------- 1: degree/count atomics + x->fp16 conversion (fused) ---------
__global__ void k_degcnt_xconv(const float* __restrict__ x,
                               const int* __restrict__ ei,
                               const float* __restrict__ ew) {
    int t = blockIdx.x * blockDim.x + threadIdx.x;
    if (t < EE) {
        int s = ei[t];
        int d = ei[EE + t];
        atomicAdd(&g_deg[s], ew[t]);
        atomicAdd(&g_cnt[d], 1);
    }
    if (t < NN * MM * 16) {
        int c2 = t & 15;
        int m = (t >> 4) & 7;
        int n = t >> 7;
        float2 v = *(const float2*)&x[((size_t)m * NN + n) * CC + c2 * 2];
        *(__half2*)&g_xh[(size_t)n * FF + m * CC + c2 * 2] =
            __floats2half2_rn(v.x, v.y);
    }
}

// ---------------- 2: scan(cnt)->rowptr  +  dinv (fused) ------------------------
__global__ void k_scan_dinv() {
    __shared__ int s_wsum[8];
    __shared__ int s_prev;
    int tid = threadIdx.x, b = blockIdx.x;
    int lane = tid & 31, w = tid >> 5;

    for (int i = b * 4096 + tid; i < (b + 1) * 4096 && i < NN; i += 256) {
        float dg = g_deg[i];
        g_dinv[i] = (dg > 0.f) ? rsqrtf(dg) : 0.f;
    }

    int base = b * 4096 + tid * 16;
    int v[16];
    int run = 0;
    #pragma unroll
    for (int j = 0; j < 16; j++) {
        int i = base + j;
        int c = 0;
        if (i < NN) { c = g_cnt[i]; g_cnt[i] = 0; }
        run += c;
        v[j] = run;   // inclusive within thread
    }
    int sc = run;
    #pragma unroll
    for (int off = 1; off < 32; off <<= 1) {
        int t2 = __shfl_up_sync(0xffffffffu, sc, off);
        if (lane >= off) sc += t2;
    }
    if (lane == 31) s_wsum[w] = sc;
    __syncthreads();
    if (w == 0) {
        int xv = (lane < 8) ? s_wsum[lane] : 0;
        #pragma unroll
        for (int off = 1; off < 8; off <<= 1) {
            int t2 = __shfl_up_sync(0xffffffffu, xv, off);
            if (lane >= off) xv += t2;
        }
        if (lane < 8) s_wsum[lane] = xv;
    }
    __syncthreads();
    int thread_excl = sc - run + (w ? s_wsum[w - 1] : 0);
    int block_total = s_wsum[7];
    if (tid == 0) {
        int prev = 0;
        if (b > 0) {
            while (((volatile int*)g_scan_flag)[b - 1] == 0) { }
            __threadfence();
            prev = g_scan_val[b - 1];
        }
        g_scan_val[b] = prev + block_total;
        __threadfence();
        ((volatile int*)g_scan_flag)[b] = 1;
        s_prev = prev;
    }
    __syncthreads();
    int off0 = s_prev + thread_excl;
    #pragma unroll
    for (int j = 0; j < 16; j++) {
        int i = base + j;
        if (i < NN) g_rowptr[i + 1] = off0 + v[j];
    }
    if (b == 0 && tid == 0) g_rowptr[0] = 0;
}

// ---------------- 3: CSR fill (edges grouped by dst), packed (src,w) -----------
__global__ void k_fill(const int* __restrict__ ei,
                       const float* __restrict__ ew) {
    int e = blockIdx.x * blockDim.x + threadIdx.x;
    if (e >= EE) return;
    int s = ei[e];
    int d = ei[EE + e];
    float nv = -g_dinv[s] * ew[e] * g_dinv[d];
    int idx = g_rowptr[d] + atomicAdd(&g_cnt[d], 1);
    g_edge[idx] = make_uint2((unsigned)s, __float_as_uint(nv));
}

// ---------------- 4/5: SpMM (fp16 gather, packed f32x2 accumulate) -------------
// One warp per dst row; lane owns 8 contiguous halves (16B = 1 uint4).
// Per edge: 1 LDG.128 + 8 cvt + 4 FFMA2, 32-bit addressing.
__device__ __forceinline__ void acc_edge2(unsigned long long* acc, uint4 v,
                                          unsigned long long w2) {
    float2 f0 = __half22float2(*(const __half2*)&v.x);
    float2 f1 = __half22float2(*(const __half2*)&v.y);
    float2 f2 = __half22float2(*(const __half2*)&v.z);
    float2 f3 = __half22float2(*(const __half2*)&v.w);
    ffma2(acc[0], pk2two(f0.x, f0.y), w2);
    ffma2(acc[1], pk2two(f1.x, f1.y), w2);
    ffma2(acc[2], pk2two(f2.x, f2.y), w2);
    ffma2(acc[3], pk2two(f3.x, f3.y), w2);
}

template <int MODE>
__global__ void __launch_bounds__(256) k_spmm_h() {
    int row = (blockIdx.x * blockDim.x + threadIdx.x) >> 5;
    int lane = threadIdx.x & 31;
    if (row >= NN) return;
    int e = g_rowptr[row];
    int end = g_rowptr[row + 1];

    const char* __restrict__ vin =
        (MODE == 0) ? (const char*)g_xh : (const char*)g_t1h;
    uint4* __restrict__ vout =
        (MODE == 0) ? (uint4*)g_t1h : (uint4*)g_t2h;

    unsigned long long acc[4] = {0ull, 0ull, 0ull, 0ull};
    unsigned lb = (unsigned)lane << 4;   // lane byte offset within node row

    #pragma unroll 1
    while (e + 4 <= end) {
        uint2 E0 = __ldcs(&g_edge[e]);
        uint2 E1 = __ldcs(&g_edge[e + 1]);
        uint2 E2 = __ldcs(&g_edge[e + 2]);
        uint2 E3 = __ldcs(&g_edge[e + 3]);
        uint4 V0 = *(const uint4*)(vin + ((E0.x << 9) + lb));
        uint4 V1 = *(const uint4*)(vin + ((E1.x << 9) + lb));
        uint4 V2 = *(const uint4*)(vin + ((E2.x << 9) + lb));
        uint4 V3 = *(const uint4*)(vin + ((E3.x << 9) + lb));
        acc_edge2(acc, V0, pk2(__uint_as_float(E0.y)));
        acc_edge2(acc, V1, pk2(__uint_as_float(E1.y)));
        acc_edge2(acc, V2, pk2(__uint_as_float(E2.y)));
        acc_edge2(acc, V3, pk2(__uint_as_float(E3.y)));
        e += 4;
    }
    #pragma unroll 1
    while (e < end) {
        uint2 E0 = __ldcs(&g_edge[e]);
        uint4 V0 = *(const uint4*)(vin + ((E0.x << 9) + lb));
        acc_edge2(acc, V0, pk2(__uint_as_float(E0.y)));
        e++;
    }

    float a0, a1, a2, a3, a4, a5, a6, a7;
    unpk2(a0, a1, acc[0]);
    unpk2(a2, a3, acc[1]);
    unpk2(a4, a5, acc[2]);
    unpk2(a6, a7, acc[3]);
    uint4 o;
    *(__half2*)&o.x = __floats2half2_rn(a0, a1);
    *(__half2*)&o.y = __floats2half2_rn(a2, a3);
    *(__half2*)&o.z = __floats2half2_rn(a4, a5);
    *(__half2*)&o.w = __floats2half2_rn(a6, a7);
    vout[(size_t)row * 32 + lane] = o;
}

// ---------------- 6: combine (Cheb matvecs + bias, FFMA2), 2 rows/thread -------
__global__ void __launch_bounds__(256) k_combine(const float* __restrict__ x,
                                                 const float* __restrict__ W,
                                                 const float* __restrict__ bias) {
    __shared__ __align__(16) float sW[3 * CC * OO + OO];  // W0,W1,W2 + bias

    for (int i = threadIdx.x; i < 3 * CC * OO + OO; i += blockDim.x)
        sW[i] = (i < 3 * CC * OO) ? W[i] : bias[i - 3 * CC * OO];
    __syncthreads();

    int t = blockIdx.x * blockDim.x + threadIdx.x;
    if (t >= NN * MM / 2) return;
    int m = t & 7;
    int n0 = (t >> 3) * 2;
    int n1 = n0 + 1;

    const float4* xp0 = (const float4*)&x[((size_t)m * NN + n0) * CC];
    const float4* xp1 = (const float4*)&x[((size_t)m * NN + n1) * CC];
    const uint4* p1a = (const uint4*)&g_t1h[(size_t)n0 * FF + m * CC];
    const uint4* p2a = (const uint4*)&g_t2h[(size_t)n0 * FF + m * CC];
    const uint4* p1b = (const uint4*)&g_t1h[(size_t)n1 * FF + m * CC];
    const uint4* p2b = (const uint4*)&g_t2h[(size_t)n1 * FF + m * CC];

    unsigned long long accA[16], accB[16];
    #pragma unroll
    for (int o = 0; o < 16; o++) {
        unsigned long long bz =
            pk2two(sW[3 * CC * OO + o * 2], sW[3 * CC * OO + o * 2 + 1]);
        accA[o] = bz;
        accB[o] = bz;
    }

    #pragma unroll
    for (int q = 0; q < 4; q++) {          // 8 channels per chunk
        float4 xa0 = xp0[q * 2], xb0 = xp0[q * 2 + 1];
        float4 xa1 = xp1[q * 2], xb1 = xp1[q * 2 + 1];
        uint4 u1a = p1a[q], u2a = p2a[q];
        uint4 u1b = p1b[q], u2b = p2b[q];
        float xs0[8] = {xa0.x, xa0.y, xa0.z, xa0.w, xb0.x, xb0.y, xb0.z, xb0.w};
        float xs1[8] = {xa1.x, xa1.y, xa1.z, xa1.w, xb1.x, xb1.y, xb1.z, xb1.w};
        float t1A[8], t2A[8], t1B[8], t2B[8];
        {
            const __half2* h1a = (const __half2*)&u1a;
            const __half2* h2a = (const __half2*)&u2a;
            const __half2* h1b = (const __half2*)&u1b;
            const __half2* h2b = (const __half2*)&u2b;
            #pragma unroll
            for (int j = 0; j < 4; j++) {
                float2 f1a = __half22float2(h1a[j]);
                float2 f2a = __half22float2(h2a[j]);
                float2 f1b = __half22float2(h1b[j]);
                float2 f2b = __half22float2(h2b[j]);
                t1A[j * 2] = f1a.x; t1A[j * 2 + 1] = f1a.y;
                t2A[j * 2] = f2a.x; t2A[j * 2 + 1] = f2a.y;
                t1B[j * 2] = f1b.x; t1B[j * 2 + 1] = f1b.y;
                t2B[j * 2] = f2b.x; t2B[j * 2 + 1] = f2b.y;
            }
        }
        #pragma unroll
        for (int j = 0; j < 8; j++) {
            int c = q * 8 + j;
            float a0 = xs0[j], b0 = t1A[j], c20 = 2.f * t2A[j] - a0;
            float a1 = xs1[j], b1 = t1B[j], c21 = 2.f * t2B[j] - a1;
            unsigned long long a0p = pk2(a0), b0p = pk2(b0), c0p = pk2(c20);
            unsigned long long a1p = pk2(a1), b1p = pk2(b1), c1p = pk2(c21);
            const ulonglong2* w0 = (const ulonglong2*)&sW[c * OO];
            const ulonglong2* w1 = (const ulonglong2*)&sW[CC * OO + c * OO];
            const ulonglong2* w2 = (const ulonglong2*)&sW[2 * CC * OO + c * OO];
            #pragma unroll
            for (int o = 0; o < 8; o++) {
                ulonglong2 u0 = w0[o], u1w = w1[o], u2w = w2[o];
                ffma2(accA[2 * o],     a0p, u0.x);
                ffma2(accA[2 * o + 1], a0p, u0.y);
                ffma2(accB[2 * o],     a1p, u0.x);
                ffma2(accB[2 * o + 1], a1p, u0.y);
                ffma2(accA[2 * o],     b0p, u1w.x);
                ffma2(accA[2 * o + 1], b0p, u1w.y);
                ffma2(accB[2 * o],     b1p, u1w.x);
                ffma2(accB[2 * o + 1], b1p, u1w.y);
                ffma2(accA[2 * o],     c0p, u2w.x);
                ffma2(accA[2 * o + 1], c0p, u2w.y);
                ffma2(accB[2 * o],     c1p, u2w.x);
                ffma2(accB[2 * o + 1], c1p, u2w.y);
            }
        }
    }

    float4* opA = (float4*)&g_outpre[(size_t)n0 * FF + m * CC];
    float4* opB = (float4*)&g_outpre[(size_t)n1 * FF + m * CC];
    #pragma unroll
    for (int o = 0; o < 8; o++) {
        float r0, r1, r2, r3;
        unpk2(r0, r1, accA[o * 2]);
        unpk2(r2, r3, accA[o * 2 + 1]);
        opA[o] = make_float4(r0, r1, r2, r3);
        unpk2(r0, r1, accB[o * 2]);
        unpk2(r2, r3, accB[o * 2 + 1]);
        opB[o] = make_float4(r0, r1, r2, r3);
    }
}

// ---------------- 7: BN statistics (streaming, coalesced) ----------------------
__global__ void k_stats() {
    int tid = threadIdx.x;
    int nbase = blockIdx.x * 256;
    int rows = NN - nbase; if (rows > 256) rows = 256;
    float s0 = 0.f, sq0 = 0.f, s1 = 0.f, sq1 = 0.f;
    const float* p = &g_outpre[(size_t)nbase * FF + tid];
    int r = 0;
    #pragma unroll 4
    for (; r + 2 <= rows; r += 2) {
        float v0 = p[(size_t)r * FF];
        float v1 = p[(size_t)(r + 1) * FF];
        s0 += v0; sq0 += v0 * v0;
        s1 += v1; sq1 += v1 * v1;
    }
    if (r < rows) {
        float v0 = p[(size_t)r * FF];
        s0 += v0; sq0 += v0 * v0;
    }
    atomicAdd(&g_bnsum[tid], s0 + s1);
    atomicAdd(&g_bnsq[tid], sq0 + sq1);
}

// ---------------- 8: finalize BN stats -> scale/shift --------------------------
__global__ void k_finalize(const float* __restrict__ gamma,
                           const float* __restrict__ beta) {
    int i = threadIdx.x;  // 0..255 = (m, o)
    if (i >= MM * OO) return;
    int o = i & 31;
    float mean = g_bnsum[i] * (1.f / NN);
    float var = g_bnsq[i] * (1.f / NN) - mean * mean;
    float sc = gamma[o] * rsqrtf(var + BN_EPS);
    g_scale[i] = sc;
    g_shift[i] = beta[o] - mean * sc;
}

// ---------------- 9: normalize + relu + transpose via shared tile ---------------
#define TN 32
#define SHF4 65   // padded row stride in float4 (64 data + 1 pad)
__global__ void k_output(float* __restrict__ out) {
    __shared__ __align__(16) float4 sh[TN * SHF4];
    __shared__ float ssc[MM * OO], ssh[MM * OO];
    int tid = threadIdx.x;
    int nbase = blockIdx.x * TN;
    int nmax = NN - nbase; if (nmax > TN) nmax = TN;

    ssc[tid] = g_scale[tid];
    ssh[tid] = g_shift[tid];

    const float4* src = (const float4*)&g_outpre[(size_t)nbase * FF];
    for (int i = tid; i < nmax * 64; i += 256) {
        int nl = i >> 6, j = i & 63;
        sh[nl * SHF4 + j] = src[i];
    }
    __syncthreads();

    for (int i = tid; i < MM * TN * 8; i += 256) {
        int m = i >> 8;
        int nl = (i >> 3) & 31;
        int o4 = i & 7;
        if (nl >= nmax) continue;
        float4 v = sh[nl * SHF4 + m * 8 + o4];
        int si = m * OO + o4 * 4;
        float4 r;
        r.x = fmaxf(0.f, v.x * ssc[si + 0] + ssh[si + 0]);
        r.y = fmaxf(0.f, v.y * ssc[si + 1] + ssh[si + 1]);
        r.z = fmaxf(0.f, v.z * ssc[si + 2] + ssh[si + 2]);
        r.w = fmaxf(0.f, v.w * ssc[si + 3] + ssh[si + 3]);
        ((float4*)out)[((size_t)m * NN + nbase + nl) * 8 + o4] = r;
    }
}

// ---------------- 10: cleanup -> restore zeroed state for next replay ----------
__global__ void k_cleanup() {
    int i = blockIdx.x * blockDim.x + threadIdx.x;
    if (i < NN) { g_deg[i] = 0.f; g_cnt[i] = 0; }
    if (i < MM * OO) { g_bnsum[i] = 0.f; g_bnsq[i] = 0.f; }
    if (i < SCAN_NBLK) { g_scan_flag[i] = 0; g_scan_val[i] = 0; }
}

// ------------------------------------------------------------------------------
extern "C" void kernel_launch(void* const* d_in, const int* in_sizes, int n_in,
                              void* d_out, int out_size) {
    const float* x      = (const float*)d_in[0];
    const int*   ei     = (const int*)d_in[1];
    const float* ew     = (const float*)d_in[2];
    const float* W      = (const float*)d_in[3];
    const float* bias   = (const float*)d_in[4];
    const float* gamma  = (const float*)d_in[5];
    const float* beta   = (const float*)d_in[6];
    float* out          = (float*)d_out;

    k_degcnt_xconv<<<(NN * MM * 16 + 255) / 256, 256>>>(x, ei, ew);  // 1
    k_scan_dinv<<<SCAN_NBLK, 256>>>();                               // 2
    k_fill<<<(EE + 255) / 256, 256>>>(ei, ew);                       // 3
    k_spmm_h<0><<<(NN * 32 + 255) / 256, 256>>>();                   // 4 <- profiled
    k_spmm_h<1><<<(NN * 32 + 255) / 256, 256>>>();                   // 5
    k_combine<<<(NN * MM / 2 + 255) / 256, 256>>>(x, W, bias);       // 6
    k_stats<<<(NN + 255) / 256, 256>>>();                            // 7
    k_finalize<<<1, 256>>>(gamma, beta);                             // 8
    k_output<<<(NN + TN - 1) / TN, 256>>>(out);                      // 9
    k_cleanup<<<(NN + 255) / 256, 256>>>();                          // 10
}

// round 11
// speedup vs baseline: 2.4518x; 1.0673x over previous
#include <cuda_runtime.h>
#include <cuda_fp16.h>
#include <stdint.h>

// Problem constants (fixed shapes for this problem instance)
#define NN 50000       // nodes
#define EE 800000      // edges
#define MM 8           // B*T
#define CC 32          // in channels
#define OO 32          // out channels
#define FF 256         // MM*CC features per node
#define BN_EPS 1e-5f
#define SCAN_NBLK 13   // ceil(NN / 4096)

// ---------------- scratch (device globals; no allocation allowed) -------------
// NOTE: launch order relies on these being zero at entry. First call uses the
// CUDA static zero-initialization; k_cleanup (last launch) re-zeroes the
// accumulated ones so every graph replay starts from identical state.
__device__ float g_deg[NN];
__device__ float g_dinv[NN];
__device__ int   g_cnt[NN];          // histogram by dst, reused as fill cursor
__device__ int   g_rowptr[NN + 1];
__device__ __align__(16) uint2 g_edge[EE];              // (src, bitcast weight)
__device__ __align__(16) __half g_xh[(size_t)NN * FF];  // x, node-major fp16
__device__ __align__(16) __half g_t1h[(size_t)NN * FF]; // L x (fp16)
__device__ __align__(16) __half g_t2h[(size_t)NN * FF]; // L(Lx) raw (fp16)
__device__ __align__(16) float g_outpre[(size_t)NN * FF]; // pre-BN [r=n*8+m][32]
__device__ float g_bnsum[MM * OO];
__device__ float g_bnsq[MM * OO];
__device__ float g_scale[MM * OO];
__device__ float g_shift[MM * OO];
__device__ int   g_scan_val[SCAN_NBLK];
__device__ int   g_scan_flag[SCAN_NBLK];

// ---------------- packed f32x2 helpers (SpMM) ----------------------------------
__device__ __forceinline__ unsigned long long pk2(float v) {
    unsigned long long r;
    asm("mov.b64 %0, {%1, %2};" : "=l"(r) : "f"(v), "f"(v));
    return r;
}
__device__ __forceinline__ unsigned long long pk2two(float lo, float hi) {
    unsigned long long r;
    asm("mov.b64 %0, {%1, %2};" : "=l"(r) : "f"(lo), "f"(hi));
    return r;
}
__device__ __forceinline__ void unpk2(float& lo, float& hi, unsigned long long v) {
    asm("mov.b64 {%0, %1}, %2;" : "=f"(lo), "=f"(hi) : "l"(v));
}
__device__ __forceinline__ void ffma2(unsigned long long& d,
                                      unsigned long long a,
                                      unsigned long long b) {
    asm("fma.rn.f32x2 %0, %1, %2, %0;" : "+l"(d) : "l"(a), "l"(b));
}

// ---------------- mma helpers ---------------------------------------------------
__device__ __forceinline__ void ldm_x4(uint32_t& r0, uint32_t& r1,
                                       uint32_t& r2, uint32_t& r3, uint32_t a) {
    asm volatile("ldmatrix.sync.aligned.m8n8.x4.shared.b16 {%0,%1,%2,%3}, [%4];"
                 : "=r"(r0), "=r"(r1), "=r"(r2), "=r"(r3) : "r"(a));
}
__device__ __forceinline__ void mma16816(float* d, uint32_t a0, uint32_t a1,
                                         uint32_t a2, uint32_t a3,
                                         uint32_t b0, uint32_t b1) {
    asm volatile(
        "mma.sync.aligned.m16n8k16.row.col.f32.f16.f16.f32 "
        "{%0,%1,%2,%3}, {%4,%5,%6,%7}, {%8,%9}, {%0,%1,%2,%3};"
        : "+f"(d[0]), "+f"(d[1]), "+f"(d[2]), "+f"(d[3])
        : "r"(a0), "r"(a1), "r"(a2), "r"(a3), "r"(b0), "r"(b1));
}

// ---------------- 1: degree/count atomics + x->fp16 conversion (fused) ---------
__global__ void k_degcnt_xconv(const float* __restrict__ x,
                               const int* __restrict__ ei,
                               const float* __restrict__ ew) {
    int t = blockIdx.x * blockDim.x + threadIdx.x;
    if (t < EE) {
        int s = ei[t];
        int d = ei[EE + t];
        atomicAdd(&g_deg[s], ew[t]);
        atomicAdd(&g_cnt[d], 1);
    }
    if (t < NN * MM * 16) {
        int c2 = t & 15;
        int m = (t >> 4) & 7;
        int n = t >> 7;
        float2 v = *(const float2*)&x[((size_t)m * NN + n) * CC + c2 * 2];
        *(__half2*)&g_xh[(size_t)n * FF + m * CC + c2 * 2] =
            __floats2half2_rn(v.x, v.y);
    }
}

// ---------------- 2: scan(cnt)->rowptr  +  dinv (fused) ------------------------
__global__ void k_scan_dinv() {
    __shared__ int s_wsum[8];
    __shared__ int s_prev;
    int tid = threadIdx.x, b = blockIdx.x;
    int lane = tid & 31, w = tid >> 5;

    for (int i = b * 4096 + tid; i < (b + 1) * 4096 && i < NN; i += 256) {
        float dg = g_deg[i];
        g_dinv[i] = (dg > 0.f) ? rsqrtf(dg) : 0.f;
    }

    int base = b * 4096 + tid * 16;
    int v[16];
    int run = 0;
    #pragma unroll
    for (int j = 0; j < 16; j++) {
        int i = base + j;
        int c = 0;
        if (i < NN) { c = g_cnt[i]; g_cnt[i] = 0; }
        run += c;
        v[j] = run;   // inclusive within thread
    }
    int sc = run;
    #pragma unroll
    for (int off = 1; off < 32; off <<= 1) {
        int t2 = __shfl_up_sync(0xffffffffu, sc, off);
        if (lane >= off) sc += t2;
    }
    if (lane == 31) s_wsum[w] = sc;
    __syncthreads();
    if (w == 0) {
        int xv = (lane < 8) ? s_wsum[lane] : 0;
        #pragma unroll
        for (int off = 1; off < 8; off <<= 1) {
            int t2 = __shfl_up_sync(0xffffffffu, xv, off);
            if (lane >= off) xv += t2;
        }
        if (lane < 8) s_wsum[lane] = xv;
    }
    __syncthreads();
    int thread_excl = sc - run + (w ? s_wsum[w - 1] : 0);
    int block_total = s_wsum[7];
    if (tid == 0) {
        int prev = 0;
        if (b > 0) {
            while (((volatile int*)g_scan_flag)[b - 1] == 0) { }
            __threadfence();
            prev = g_scan_val[b - 1];
        }
        g_scan_val[b] = prev + block_total;
        __threadfence();
        ((volatile int*)g_scan_flag)[b] = 1;
        s_prev = prev;
    }
    __syncthreads();
    int off0 = s_prev + thread_excl;
    #pragma unroll
    for (int j = 0; j < 16; j++) {
        int i = base + j;
        if (i < NN) g_rowptr[i + 1] = off0 + v[j];
    }
    if (b == 0 && tid == 0) g_rowptr[0] = 0;
}

// ---------------- 3: CSR fill (edges grouped by dst), packed (src,w) -----------
__global__ void k_fill(const int* __restrict__ ei,
                       const float* __restrict__ ew) {
    int e = blockIdx.x * blockDim.x + threadIdx.x;
    if (e >= EE) return;
    int s = ei[e];
    int d = ei[EE + e];
    float nv = -g_dinv[s] * ew[e] * g_dinv[d];
    int idx = g_rowptr[d] + atomicAdd(&g_cnt[d], 1);
    g_edge[idx] = make_uint2((unsigned)s, __float_as_uint(nv));
}

// ---------------- 4/5: SpMM (fp16 gather, packed f32x2 accumulate) -------------
__device__ __forceinline__ void acc_edge2(unsigned long long* acc, uint4 v,
                                          unsigned long long w2) {
    float2 f0 = __half22float2(*(const __half2*)&v.x);
    float2 f1 = __half22float2(*(const __half2*)&v.y);
    float2 f2 = __half22float2(*(const __half2*)&v.z);
    float2 f3 = __half22float2(*(const __half2*)&v.w);
    ffma2(acc[0], pk2two(f0.x, f0.y), w2);
    ffma2(acc[1], pk2two(f1.x, f1.y), w2);
    ffma2(acc[2], pk2two(f2.x, f2.y), w2);
    ffma2(acc[3], pk2two(f3.x, f3.y), w2);
}

template <int MODE>
__global__ void __launch_bounds__(256) k_spmm_h() {
    int row = (blockIdx.x * blockDim.x + threadIdx.x) >> 5;
    int lane = threadIdx.x & 31;
    if (row >= NN) return;
    int e = g_rowptr[row];
    int end = g_rowptr[row + 1];

    const char* __restrict__ vin =
        (MODE == 0) ? (const char*)g_xh : (const char*)g_t1h;
    uint4* __restrict__ vout =
        (MODE == 0) ? (uint4*)g_t1h : (uint4*)g_t2h;

    unsigned long long acc[4] = {0ull, 0ull, 0ull, 0ull};
    unsigned lb = (unsigned)lane << 4;   // lane byte offset within node row

    #pragma unroll 1
    while (e + 4 <= end) {
        uint2 E0 = __ldcs(&g_edge[e]);
        uint2 E1 = __ldcs(&g_edge[e + 1]);
        uint2 E2 = __ldcs(&g_edge[e + 2]);
        uint2 E3 = __ldcs(&g_edge[e + 3]);
        uint4 V0 = *(const uint4*)(vin + ((E0.x << 9) + lb));
        uint4 V1 = *(const uint4*)(vin + ((E1.x << 9) + lb));
        uint4 V2 = *(const uint4*)(vin + ((E2.x << 9) + lb));
        uint4 V3 = *(const uint4*)(vin + ((E3.x << 9) + lb));
        acc_edge2(acc, V0, pk2(__uint_as_float(E0.y)));
        acc_edge2(acc, V1, pk2(__uint_as_float(E1.y)));
        acc_edge2(acc, V2, pk2(__uint_as_float(E2.y)));
        acc_edge2(acc, V3, pk2(__uint_as_float(E3.y)));
        e += 4;
    }
    #pragma unroll 1
    while (e < end) {
        uint2 E0 = __ldcs(&g_edge[e]);
        uint4 V0 = *(const uint4*)(vin + ((E0.x << 9) + lb));
        acc_edge2(acc, V0, pk2(__uint_as_float(E0.y)));
        e++;
    }

    float a0, a1, a2, a3, a4, a5, a6, a7;
    unpk2(a0, a1, acc[0]);
    unpk2(a2, a3, acc[1]);
    unpk2(a4, a5, acc[2]);
    unpk2(a6, a7, acc[3]);
    uint4 o;
    *(__half2*)&o.x = __floats2half2_rn(a0, a1);
    *(__half2*)&o.y = __floats2half2_rn(a2, a3);
    *(__half2*)&o.z = __floats2half2_rn(a4, a5);
    *(__half2*)&o.w = __floats2half2_rn(a6, a7);
    vout[(size_t)row * 32 + lane] = o;
}

// ---------------- 6: combine via tensor cores (mma.sync m16n8k16) --------------
// out[r,:] = x[r]@(W0-W2) + t1[r]@W1 + t2[r]@(2*W2) + bias,  r = n*8+m.
// All three A-buffers are row-major [r][32] fp16. Block = 128 rows, 8 warps,
// warp = 16 rows x 32 cols. A staged in smem with 104-half row stride
// (conflict-free ldmatrix); Wt staged as [o][96] fp16 (col-frag LDS.32 pairs).
#define SAS 104   // smem row stride in halves (96 data + 8 pad)
__global__ void __launch_bounds__(256) k_combine_mma(const float* __restrict__ W,
                                                     const float* __restrict__ bias) {
    __shared__ __align__(16) __half sA[128 * SAS];
    __shared__ __align__(16) __half sW[32 * SAS];
    __shared__ float sB[OO];
    int tid = threadIdx.x;

    // weight prep: Wt[o][k]: k<32 -> W0-W2, k<64 -> W1, else 2*W2
    for (int i = tid; i < 32 * 96; i += 256) {
        int o = i / 96, k = i % 96;
        float v;
        if (k < 32)      v = W[k * 32 + o] - W[2048 + k * 32 + o];
        else if (k < 64) v = W[1024 + (k - 32) * 32 + o];
        else             v = 2.f * W[2048 + (k - 64) * 32 + o];
        sW[o * SAS + k] = __float2half_rn(v);
    }
    if (tid < OO) sB[tid] = bias[tid];

    // stage A rows: 128 rows x (x|t1|t2) = 128 x 96 halves
    int rbase = blockIdx.x * 128;
    const uint4* gx = (const uint4*)g_xh + (size_t)rbase * 4;
    const uint4* g1 = (const uint4*)g_t1h + (size_t)rbase * 4;
    const uint4* g2 = (const uint4*)g_t2h + (size_t)rbase * 4;
    for (int i = tid; i < 512; i += 256) {   // 128 rows x 4 16B-chunks
        int rl = i >> 2, q = i & 3;
        *(uint4*)&sA[rl * SAS + q * 8]      = gx[i];
        *(uint4*)&sA[rl * SAS + 32 + q * 8] = g1[i];
        *(uint4*)&sA[rl * SAS + 64 + q * 8] = g2[i];
    }
    __syncthreads();

    int w = tid >> 5, l = tid & 31;
    int colb = (l & 3) * 2;

    float d[4][4];
    #pragma unroll
    for (int t = 0; t < 4; t++) {
        float b0 = sB[t * 8 + colb], b1 = sB[t * 8 + colb + 1];
        d[t][0] = b0; d[t][1] = b1; d[t][2] = b0; d[t][3] = b1;
    }

    // ldmatrix quadrant address (per lane): quad0: rows0-7/k0; quad1: rows8-15/k0;
    // quad2: rows0-7/k0+8; quad3: rows8-15/k0+8
    int rowi = l & 7;
    int quad = l >> 3;
    int r_loc = w * 16 + rowi + (quad & 1) * 8;
    int cq = (quad >> 1) * 8;
    uint32_t abase = (uint32_t)__cvta_generic_to_shared(&sA[r_loc * SAS + cq]);

    #pragma unroll
    for (int ks = 0; ks < 6; ks++) {
        int c0 = ks * 16;
        uint32_t a0, a1, a2, a3;
        ldm_x4(a0, a1, a2, a3, abase + c0 * 2);
        #pragma unroll
        for (int t = 0; t < 4; t++) {
            int n = t * 8 + (l >> 2);
            uint32_t b0 = *(const uint32_t*)&sW[n * SAS + c0 + colb];
            uint32_t b1 = *(const uint32_t*)&sW[n * SAS + c0 + 8 + colb];
            mma16816(d[t], a0, a1, a2, a3, b0, b1);
        }
    }

    // store D: rows r0 (l>>2) and r0+8; cols t*8 + colb (+1)
    int r0 = rbase + w * 16 + (l >> 2);
    #pragma unroll
    for (int t = 0; t < 4; t++) {
        int c = t * 8 + colb;
        *(float2*)&g_outpre[(size_t)r0 * 32 + c] = make_float2(d[t][0], d[t][1]);
        *(float2*)&g_outpre[(size_t)(r0 + 8) * 32 + c] = make_float2(d[t][2], d[t][3]);
    }
}

// ---------------- 7: BN statistics (streaming, coalesced) ----------------------
__global__ void k_stats() {
    int tid = threadIdx.x;
    int nbase = blockIdx.x * 256;
    int rows = NN - nbase; if (rows > 256) rows = 256;
    float s0 = 0.f, sq0 = 0.f, s1 = 0.f, sq1 = 0.f;
    const float* p = &g_outpre[(size_t)nbase * FF + tid];
    int r = 0;
    #pragma unroll 4
    for (; r + 2 <= rows; r += 2) {
        float v0 = p[(size_t)r * FF];
        float v1 = p[(size_t)(r + 1) * FF];
        s0 += v0; sq0 += v0 * v0;
        s1 += v1; sq1 += v1 * v1;
    }
    if (r < rows) {
        float v0 = p[(size_t)r * FF];
        s0 += v0; sq0 += v0 * v0;
    }
    atomicAdd(&g_bnsum[tid], s0 + s1);
    atomicAdd(&g_bnsq[tid], sq0 + sq1);
}

// ---------------- 8: finalize BN stats -> scale/shift --------------------------
__global__ void k_finalize(const float* __restrict__ gamma,
                           const float* __restrict__ beta) {
    int i = threadIdx.x;  // 0..255 = (m, o)
    if (i >= MM * OO) return;
    int o = i & 31;
    float mean = g_bnsum[i] * (1.f / NN);
    float var = g_bnsq[i] * (1.f / NN) - mean * mean;
    float sc = gamma[o] * rsqrtf(var + BN_EPS);
    g_scale[i] = sc;
    g_shift[i] = beta[o] - mean * sc;
}

// ---------------- 9: normalize + relu + transpose via shared tile ---------------
#define TN 32
#define SHF4 65   // padded row stride in float4 (64 data + 1 pad)
__global__ void k_output(float* __restrict__ out) {
    __shared__ __align__(16) float4 sh[TN * SHF4];
    __shared__ float ssc[MM * OO], ssh[MM * OO];
    int tid = threadIdx.x;
    int nbase = blockIdx.x * TN;
    int nmax = NN - nbase; if (nmax > TN) nmax = TN;

    ssc[tid] = g_scale[tid];
    ssh[tid] = g_shift[tid];

    const float4* src = (const float4*)&g_outpre[(size_t)nbase * FF];
    for (int i = tid; i < nmax * 64; i += 256) {
        int nl = i >> 6, j = i & 63;
        sh[nl * SHF4 + j] = src[i];
    }
    __syncthreads();

    for (int i = tid; i < MM * TN * 8; i += 256) {
        int m = i >> 8;
        int nl = (i >> 3) & 31;
        int o4 = i & 7;
        if (nl >= nmax) continue;
        float4 v = sh[nl * SHF4 + m * 8 + o4];
        int si = m * OO + o4 * 4;
        float4 r;
        r.x = fmaxf(0.f, v.x * ssc[si + 0] + ssh[si + 0]);
        r.y = fmaxf(0.f, v.y * ssc[si + 1] + ssh[si + 1]);
        r.z = fmaxf(0.f, v.z * ssc[si + 2] + ssh[si + 2]);
        r.w = fmaxf(0.f, v.w * ssc[si + 3] + ssh[si + 3]);
        ((float4*)out)[((size_t)m * NN + nbase + nl) * 8 + o4] = r;
    }
}

// ---------------- 10: cleanup -> restore zeroed state for next replay ----------
__global__ void k_cleanup() {
    int i = blockIdx.x * blockDim.x + threadIdx.x;
    if (i < NN) { g_deg[i] = 0.f; g_cnt[i] = 0; }
    if (i < MM * OO) { g_bnsum[i] = 0.f; g_bnsq[i] = 0.f; }
    if (i < SCAN_NBLK) { g_scan_flag[i] = 0; g_scan_val[i] = 0; }
}

// ------------------------------------------------------------------------------
extern "C" void kernel_launch(void* const* d_in, const int* in_sizes, int n_in,
                              void* d_out, int out_size) {
    const float* x      = (const float*)d_in[0];
    const int*   ei     = (const int*)d_in[1];
    const float* ew     = (const float*)d_in[2];
    const float* W      = (const float*)d_in[3];
    const float* bias   = (const float*)d_in[4];
    const float* gamma  = (const float*)d_in[5];
    const float* beta   = (const float*)d_in[6];
    float* out          = (float*)d_out;

    k_degcnt_xconv<<<(NN * MM * 16 + 255) / 256, 256>>>(x, ei, ew);  // 1
    k_scan_dinv<<<SCAN_NBLK, 256>>>();                               // 2
    k_fill<<<(EE + 255) / 256, 256>>>(ei, ew);                       // 3
    k_spmm_h<0><<<(NN * 32 + 255) / 256, 256>>>();                   // 4 <- profiled
    k_spmm_h<1><<<(NN * 32 + 255) / 256, 256>>>();                   // 5
    k_combine_mma<<<(NN * MM) / 128, 256>>>(W, bias);                // 6
    k_stats<<<(NN + 255) / 256, 256>>>();                            // 7
    k_finalize<<<1, 256>>>(gamma, beta);                             // 8
    k_output<<<(NN + TN - 1) / TN, 256>>>(out);                      // 9
    k_cleanup<<<(NN + 255) / 256, 256>>>();                          // 10
}